// round 3
// baseline (speedup 1.0000x reference)
#include <cuda_runtime.h>

#define MAX_NODES 100000
#define INDIM 128
#define HID 64

typedef unsigned long long u64;

// Scratch: per-node projections P[n][0:64]=z@W1a + b1, P[n][64:128]=z@W1b
__device__ float g_P[MAX_NODES * 128];

// ---------------------------------------------------------------------------
// f32x2 packed helpers (Blackwell — ptxas won't auto-fuse, PTX only)
__device__ __forceinline__ u64 pack2(float lo, float hi) {
    u64 r;
    asm("mov.b64 %0, {%1, %2};" : "=l"(r) : "f"(lo), "f"(hi));
    return r;
}
__device__ __forceinline__ void unpack2(u64 v, float& lo, float& hi) {
    asm("mov.b64 {%0, %1}, %2;" : "=f"(lo), "=f"(hi) : "l"(v));
}
__device__ __forceinline__ void ffma2(u64& d, u64 a, u64 b) {
    asm("fma.rn.f32x2 %0, %1, %2, %0;" : "+l"(d) : "l"(a), "l"(b));
}
__device__ __forceinline__ u64 fadd2(u64 a, u64 b) {
    u64 r;
    asm("add.rn.f32x2 %0, %1, %2;" : "=l"(r) : "l"(a), "l"(b));
    return r;
}

// ---------------------------------------------------------------------------
// Precompute GEMM: P[100K,128] = z[100K,128] @ Wcat[128,128]  (+ b1 on cols 0..63)
__global__ __launch_bounds__(256) void precompute_kernel(
    const float* __restrict__ z, const float* __restrict__ W1,
    const float* __restrict__ b1, int n_nodes)
{
    __shared__ __align__(16) float zs[32 * 132];
    __shared__ __align__(16) float ws[32 * 128];

    const int tid = threadIdx.x;
    const int g   = tid >> 4;
    const int c   = tid & 15;
    const int c0  = c * 8;
    const int nb  = blockIdx.x * 128;

    u64 acc2[8][4];
#pragma unroll
    for (int i = 0; i < 8; i++)
#pragma unroll
        for (int j = 0; j < 4; j++) acc2[i][j] = 0ull;

    for (int kc = 0; kc < 4; kc++) {
        __syncthreads();
        for (int idx = tid; idx < 128 * 32; idx += 256) {
            int n  = idx >> 5;
            int kq = idx & 31;
            int row = nb + n;
            float v = (row < n_nodes) ? z[(size_t)row * 128 + kc * 32 + kq] : 0.f;
            zs[kq * 132 + n] = v;
        }
        for (int idx = tid; idx < 32 * 128; idx += 256) {
            int kl = idx >> 7;
            int o  = idx & 127;
            int kk = kc * 32 + kl;
            float wv = (o < 64) ? W1[kk * 64 + o] : W1[(128 + kk) * 64 + (o - 64)];
            ws[idx] = wv;
        }
        __syncthreads();

#pragma unroll
        for (int k = 0; k < 32; k++) {
            float4 a0 = *(const float4*)&zs[k * 132 + g * 8];
            float4 a1 = *(const float4*)&zs[k * 132 + g * 8 + 4];
            ulonglong2 bv0 = *(const ulonglong2*)&ws[k * 128 + c0];
            ulonglong2 bv1 = *(const ulonglong2*)&ws[k * 128 + c0 + 4];
            float a[8] = {a0.x, a0.y, a0.z, a0.w, a1.x, a1.y, a1.z, a1.w};
#pragma unroll
            for (int i = 0; i < 8; i++) {
                u64 ad = pack2(a[i], a[i]);
                ffma2(acc2[i][0], ad, bv0.x);
                ffma2(acc2[i][1], ad, bv0.y);
                ffma2(acc2[i][2], ad, bv1.x);
                ffma2(acc2[i][3], ad, bv1.y);
            }
        }
    }

    float bias[8];
#pragma unroll
    for (int j = 0; j < 8; j++) bias[j] = (c0 < 64) ? b1[c0 + j] : 0.f;

#pragma unroll
    for (int i = 0; i < 8; i++) {
        int row = nb + g * 8 + i;
        if (row < n_nodes) {
            float v[8];
#pragma unroll
            for (int j = 0; j < 4; j++) unpack2(acc2[i][j], v[2 * j], v[2 * j + 1]);
            float4 o0 = make_float4(v[0] + bias[0], v[1] + bias[1],
                                    v[2] + bias[2], v[3] + bias[3]);
            float4 o1 = make_float4(v[4] + bias[4], v[5] + bias[5],
                                    v[6] + bias[6], v[7] + bias[7]);
            *(float4*)&g_P[(size_t)row * 128 + c0]     = o0;
            *(float4*)&g_P[(size_t)row * 128 + c0 + 4] = o1;
        }
    }
}

// ---------------------------------------------------------------------------
__device__ __forceinline__ int2 load_edge(const void* eidx, bool is64, int e, int E) {
    if (is64) {
        long long i = ((const long long*)eidx)[e];
        long long j = ((const long long*)eidx)[(long long)E + e];
        return make_int2((int)i, (int)j);
    } else {
        return make_int2(((const int*)eidx)[e], ((const int*)eidx)[E + e]);
    }
}

// Edge kernel: warp per edge (grid-strided). W2 column per lane in 32 f32x2
// regs. Software pipeline: P rows prefetched 2 edges ahead, indices 3 ahead.
// Layer 2 uses 4 independent f32x2 accumulators (short RAW chains).
// h1 staged through double-buffered smem -> one syncwarp per edge.
__global__ __launch_bounds__(256) void edge_kernel(
    const void* __restrict__ eidx,
    const float* __restrict__ W2, const float* __restrict__ b2,
    const float* __restrict__ W3, const float* __restrict__ b3,
    float* __restrict__ out, int E)
{
    __shared__ __align__(16) u64 h1s[8][2][32];  // [warp][buf][pair]
    const int lane = threadIdx.x & 31;
    const int wid  = threadIdx.x >> 5;
    const int gw   = (blockIdx.x * blockDim.x + threadIdx.x) >> 5;
    const int GW   = (gridDim.x * blockDim.x) >> 5;

    // int64 vs int32 edge_index detection (warp-parallel):
    // LE int64 values < 100000 -> every odd 32-bit word is zero.
    const int* ei32 = (const int*)eidx;
    int oddw = ei32[2 * lane + 1] | ei32[2 * lane + 65];
    const bool is64 = (__ballot_sync(0xffffffffu, oddw != 0) == 0u);

    // per-lane W2 column packed along k
    u64 w2p[32];
#pragma unroll
    for (int k2 = 0; k2 < 32; k2++)
        w2p[k2] = pack2(W2[(2 * k2) * 32 + lane], W2[(2 * k2 + 1) * 32 + lane]);
    const float b2r = b2[lane];
    const float w3r = W3[lane];
    const float b3v = b3[0];

    const char* __restrict__ Pb = (const char*)g_P;
    const unsigned lane8 = (unsigned)lane * 8u;

    const int Em1 = E - 1;
    int e  = gw;
    int e1 = e + GW;
    int e2 = e1 + GW;

    int2 ij0 = load_edge(eidx, is64, min(e, Em1), E);
    int2 ij1 = load_edge(eidx, is64, min(e1, Em1), E);
    u64 pa = *(const u64*)(Pb + (unsigned)ij0.x * 512u + lane8);
    u64 pb = *(const u64*)(Pb + (unsigned)ij0.y * 512u + 256u + lane8);
    u64 qa = *(const u64*)(Pb + (unsigned)ij1.x * 512u + lane8);
    u64 qb = *(const u64*)(Pb + (unsigned)ij1.y * 512u + 256u + lane8);
    int2 ij2 = load_edge(eidx, is64, min(e2, Em1), E);

    int buf = 0;
    while (e < E) {
        // issue P-row loads for edge e2 (2 ahead)
        u64 ra = *(const u64*)(Pb + (unsigned)ij2.x * 512u + lane8);
        u64 rb = *(const u64*)(Pb + (unsigned)ij2.y * 512u + 256u + lane8);
        // indices 3 ahead
        int e3 = e2 + GW;
        int2 ij3 = load_edge(eidx, is64, min(e3, Em1), E);

        // layer 1: packed add + relu (b1 pre-folded into P's first half)
        u64 hsum = fadd2(pa, pb);
        float hx, hy;
        unpack2(hsum, hx, hy);
        h1s[wid][buf][lane] = pack2(fmaxf(hx, 0.f), fmaxf(hy, 0.f));
        __syncwarp();

        // layer 2: 4 independent f32x2 accumulators
        u64 a0 = pack2(b2r, 0.f), a1 = 0ull, a2 = 0ull, a3 = 0ull;
        const ulonglong2* hq = (const ulonglong2*)h1s[wid][buf];
#pragma unroll
        for (int k = 0; k < 8; k++) {
            ulonglong2 hA = hq[2 * k];
            ulonglong2 hB = hq[2 * k + 1];
            ffma2(a0, hA.x, w2p[4 * k + 0]);
            ffma2(a1, hA.y, w2p[4 * k + 1]);
            ffma2(a2, hB.x, w2p[4 * k + 2]);
            ffma2(a3, hB.y, w2p[4 * k + 3]);
        }
        a0 = fadd2(a0, a1);
        a2 = fadd2(a2, a3);
        a0 = fadd2(a0, a2);
        float alo, ahi;
        unpack2(a0, alo, ahi);

        // layer 3 + sigmoid
        float p = fmaxf(alo + ahi, 0.f) * w3r;
        p += __shfl_xor_sync(0xffffffffu, p, 16);
        p += __shfl_xor_sync(0xffffffffu, p, 8);
        p += __shfl_xor_sync(0xffffffffu, p, 4);
        p += __shfl_xor_sync(0xffffffffu, p, 2);
        p += __shfl_xor_sync(0xffffffffu, p, 1);
        if (lane == 0) {
            float logit = p + b3v;
            out[e] = __fdividef(1.f, 1.f + __expf(-logit));
        }

        // rotate pipeline
        pa = qa; pb = qb; qa = ra; qb = rb;
        ij2 = ij3;
        e = e1; e1 = e2; e2 = e3;
        buf ^= 1;
    }
}

// ---------------------------------------------------------------------------
extern "C" void kernel_launch(void* const* d_in, const int* in_sizes, int n_in,
                              void* d_out, int out_size)
{
    const float* z  = (const float*)d_in[0];
    const void*  ei = d_in[1];
    const float* W1 = (const float*)d_in[2];
    const float* b1 = (const float*)d_in[3];
    const float* W2 = (const float*)d_in[4];
    const float* b2 = (const float*)d_in[5];
    const float* W3 = (const float*)d_in[6];
    const float* b3 = (const float*)d_in[7];
    float* out = (float*)d_out;

    int n_nodes = in_sizes[0] / INDIM;
    if (n_nodes > MAX_NODES) n_nodes = MAX_NODES;
    int E = out_size;

    int gblocks = (n_nodes + 127) / 128;
    precompute_kernel<<<gblocks, 256>>>(z, W1, b1, n_nodes);
    edge_kernel<<<296, 256>>>(ei, W2, b2, W3, b3, out, E);
}

// round 5
// speedup vs baseline: 1.4345x; 1.4345x over previous
#include <cuda_runtime.h>

#define MAX_NODES 100000
#define INDIM 128
#define HID 64

typedef unsigned long long u64;

// Scratch: per-node projections P[n][0:64]=z@W1a + b1, P[n][64:128]=z@W1b
__device__ float g_P[MAX_NODES * 128];

// ---------------------------------------------------------------------------
// f32x2 packed helpers (Blackwell — ptxas won't auto-fuse, PTX only)
__device__ __forceinline__ u64 pack2(float lo, float hi) {
    u64 r;
    asm("mov.b64 %0, {%1, %2};" : "=l"(r) : "f"(lo), "f"(hi));
    return r;
}
__device__ __forceinline__ void unpack2(u64 v, float& lo, float& hi) {
    asm("mov.b64 {%0, %1}, %2;" : "=f"(lo), "=f"(hi) : "l"(v));
}
__device__ __forceinline__ void ffma2(u64& d, u64 a, u64 b) {
    asm("fma.rn.f32x2 %0, %1, %2, %0;" : "+l"(d) : "l"(a), "l"(b));
}
__device__ __forceinline__ u64 fadd2(u64 a, u64 b) {
    u64 r;
    asm("add.rn.f32x2 %0, %1, %2;" : "=l"(r) : "l"(a), "l"(b));
    return r;
}

// ---------------------------------------------------------------------------
// Precompute GEMM: P[100K,128] = z[100K,128] @ Wcat[128,128]  (+ b1 on cols 0..63)
__global__ __launch_bounds__(256) void precompute_kernel(
    const float* __restrict__ z, const float* __restrict__ W1,
    const float* __restrict__ b1, int n_nodes)
{
    __shared__ __align__(16) float zs[32 * 132];
    __shared__ __align__(16) float ws[32 * 128];

    const int tid = threadIdx.x;
    const int g   = tid >> 4;
    const int c   = tid & 15;
    const int c0  = c * 8;
    const int nb  = blockIdx.x * 128;

    u64 acc2[8][4];
#pragma unroll
    for (int i = 0; i < 8; i++)
#pragma unroll
        for (int j = 0; j < 4; j++) acc2[i][j] = 0ull;

    for (int kc = 0; kc < 4; kc++) {
        __syncthreads();
        for (int idx = tid; idx < 128 * 32; idx += 256) {
            int n  = idx >> 5;
            int kq = idx & 31;
            int row = nb + n;
            float v = (row < n_nodes) ? z[(size_t)row * 128 + kc * 32 + kq] : 0.f;
            zs[kq * 132 + n] = v;
        }
        for (int idx = tid; idx < 32 * 128; idx += 256) {
            int kl = idx >> 7;
            int o  = idx & 127;
            int kk = kc * 32 + kl;
            float wv = (o < 64) ? W1[kk * 64 + o] : W1[(128 + kk) * 64 + (o - 64)];
            ws[idx] = wv;
        }
        __syncthreads();

#pragma unroll
        for (int k = 0; k < 32; k++) {
            float4 a0 = *(const float4*)&zs[k * 132 + g * 8];
            float4 a1 = *(const float4*)&zs[k * 132 + g * 8 + 4];
            ulonglong2 bv0 = *(const ulonglong2*)&ws[k * 128 + c0];
            ulonglong2 bv1 = *(const ulonglong2*)&ws[k * 128 + c0 + 4];
            float a[8] = {a0.x, a0.y, a0.z, a0.w, a1.x, a1.y, a1.z, a1.w};
#pragma unroll
            for (int i = 0; i < 8; i++) {
                u64 ad = pack2(a[i], a[i]);
                ffma2(acc2[i][0], ad, bv0.x);
                ffma2(acc2[i][1], ad, bv0.y);
                ffma2(acc2[i][2], ad, bv1.x);
                ffma2(acc2[i][3], ad, bv1.y);
            }
        }
    }

    float bias[8];
#pragma unroll
    for (int j = 0; j < 8; j++) bias[j] = (c0 < 64) ? b1[c0 + j] : 0.f;

#pragma unroll
    for (int i = 0; i < 8; i++) {
        int row = nb + g * 8 + i;
        if (row < n_nodes) {
            float v[8];
#pragma unroll
            for (int j = 0; j < 4; j++) unpack2(acc2[i][j], v[2 * j], v[2 * j + 1]);
            float4 o0 = make_float4(v[0] + bias[0], v[1] + bias[1],
                                    v[2] + bias[2], v[3] + bias[3]);
            float4 o1 = make_float4(v[4] + bias[4], v[5] + bias[5],
                                    v[6] + bias[6], v[7] + bias[7]);
            *(float4*)&g_P[(size_t)row * 128 + c0]     = o0;
            *(float4*)&g_P[(size_t)row * 128 + c0 + 4] = o1;
        }
    }
}

// ---------------------------------------------------------------------------
// Edge kernel: each warp processes batches of 32 consecutive edges.
//  - batch indices loaded coalesced (one LDG per lane), broadcast by shfl
//  - per edge: layer1 (packed add+relu) -> h1 smem (double buf) -> layer2
//    (lane = neuron, W2 column in 64 regs, 4 indep f32x2 accumulators),
//    relu'd h2 stored to h2s[edge][lane]
//  - after 32 edges: ONE syncwarp, then lane e does layer3+sigmoid for edge e
//    fully in-lane (no shfl reduction), coalesced STG.
__global__ __launch_bounds__(256) void edge_kernel(
    const void* __restrict__ eidx,
    const float* __restrict__ W2, const float* __restrict__ b2,
    const float* __restrict__ W3, const float* __restrict__ b3,
    float* __restrict__ out, int E)
{
    __shared__ __align__(16) u64   h1s[8][2][32];    // [warp][buf][pair]
    __shared__ __align__(16) float h2s[8][32][36];   // [warp][edge][neuron], pad 36
    __shared__ __align__(16) float w3s[32];

    const int lane = threadIdx.x & 31;
    const int wid  = threadIdx.x >> 5;
    const int gw   = (blockIdx.x * blockDim.x + threadIdx.x) >> 5;
    const int GW   = (gridDim.x * blockDim.x) >> 5;
    const int STRIDE = GW * 32;

    if (threadIdx.x < 32) w3s[threadIdx.x] = W3[threadIdx.x];

    // int64 vs int32 edge_index detection: LE int64 < 100000 -> odd words zero
    const int* ei32 = (const int*)eidx;
    int oddw = ei32[2 * lane + 1] | ei32[2 * lane + 65];
    const bool is64 = (__ballot_sync(0xffffffffu, oddw != 0) == 0u);

    // per-lane W2 column packed along k (lane = output neuron)
    u64 w2p[32];
#pragma unroll
    for (int k2 = 0; k2 < 32; k2++)
        w2p[k2] = pack2(W2[(2 * k2) * 32 + lane], W2[(2 * k2 + 1) * 32 + lane]);
    const float b2r = b2[lane];
    const float b3v = b3[0];

    const char* __restrict__ Pb = (const char*)g_P;
    const unsigned lane8 = (unsigned)lane * 8u;
    const int Em1 = E - 1;

    __syncthreads();  // w3s visible

    for (int b = gw * 32; b < E; b += STRIDE) {
        // coalesced batch index load (clamped)
        int me = min(b + lane, Em1);
        int iL, jL;
        if (is64) {
            iL = (int)((const long long*)eidx)[me];
            jL = (int)((const long long*)eidx)[(long long)E + me];
        } else {
            iL = ((const int*)eidx)[me];
            jL = ((const int*)eidx)[E + me];
        }

        // prologue: P rows for edges 0,1
        int i0 = __shfl_sync(0xffffffffu, iL, 0);
        int j0 = __shfl_sync(0xffffffffu, jL, 0);
        int i1 = __shfl_sync(0xffffffffu, iL, 1);
        int j1 = __shfl_sync(0xffffffffu, jL, 1);
        u64 pa = *(const u64*)(Pb + (unsigned)i0 * 512u + lane8);
        u64 pb = *(const u64*)(Pb + (unsigned)j0 * 512u + 256u + lane8);
        u64 qa = *(const u64*)(Pb + (unsigned)i1 * 512u + lane8);
        u64 qb = *(const u64*)(Pb + (unsigned)j1 * 512u + 256u + lane8);

        int buf = 0;
        for (int e = 0; e < 32; e++) {
            // prefetch P rows for edge e+2
            u64 ra = pa, rb = pb;
            int en = e + 2;
            if (en < 32) {
                int ii = __shfl_sync(0xffffffffu, iL, en);
                int jj = __shfl_sync(0xffffffffu, jL, en);
                ra = *(const u64*)(Pb + (unsigned)ii * 512u + lane8);
                rb = *(const u64*)(Pb + (unsigned)jj * 512u + 256u + lane8);
            }

            // layer 1: packed add + relu (b1 pre-folded into P's first half)
            float hx, hy;
            unpack2(fadd2(pa, pb), hx, hy);
            h1s[wid][buf][lane] = pack2(fmaxf(hx, 0.f), fmaxf(hy, 0.f));
            __syncwarp();

            // layer 2: 4 independent f32x2 accumulators
            u64 a0 = pack2(b2r, 0.f), a1 = 0ull, a2 = 0ull, a3 = 0ull;
            const ulonglong2* hq = (const ulonglong2*)h1s[wid][buf];
#pragma unroll
            for (int k = 0; k < 8; k++) {
                ulonglong2 hA = hq[2 * k];
                ulonglong2 hB = hq[2 * k + 1];
                ffma2(a0, hA.x, w2p[4 * k + 0]);
                ffma2(a1, hA.y, w2p[4 * k + 1]);
                ffma2(a2, hB.x, w2p[4 * k + 2]);
                ffma2(a3, hB.y, w2p[4 * k + 3]);
            }
            a0 = fadd2(fadd2(a0, a1), fadd2(a2, a3));
            float lo, hi;
            unpack2(a0, lo, hi);
            h2s[wid][e][lane] = fmaxf(lo + hi, 0.f);  // relu'd, no sync needed yet

            // rotate pipeline
            pa = qa; pb = qb; qa = ra; qb = rb;
            buf ^= 1;
        }
        __syncwarp();

        // layer 3: lane handles edge b+lane entirely in-lane (no reductions)
        {
            const ulonglong2* hrow = (const ulonglong2*)&h2s[wid][lane][0];
            const ulonglong2* w3p  = (const ulonglong2*)w3s;
            u64 c0 = 0ull, c1 = 0ull, c2 = 0ull, c3 = 0ull;
#pragma unroll
            for (int q = 0; q < 4; q++) {
                ulonglong2 h = hrow[2 * q];
                ulonglong2 g = hrow[2 * q + 1];
                ulonglong2 w = w3p[2 * q];
                ulonglong2 v = w3p[2 * q + 1];
                ffma2(c0, h.x, w.x);
                ffma2(c1, h.y, w.y);
                ffma2(c2, g.x, v.x);
                ffma2(c3, g.y, v.y);
            }
            c0 = fadd2(fadd2(c0, c1), fadd2(c2, c3));
            float lo, hi;
            unpack2(c0, lo, hi);
            float logit = lo + hi + b3v;
            float sig = __fdividef(1.f, 1.f + __expf(-logit));
            if (b + lane < E) out[b + lane] = sig;
        }
        __syncwarp();
    }
}

// ---------------------------------------------------------------------------
extern "C" void kernel_launch(void* const* d_in, const int* in_sizes, int n_in,
                              void* d_out, int out_size)
{
    const float* z  = (const float*)d_in[0];
    const void*  ei = d_in[1];
    const float* W1 = (const float*)d_in[2];
    const float* b1 = (const float*)d_in[3];
    const float* W2 = (const float*)d_in[4];
    const float* b2 = (const float*)d_in[5];
    const float* W3 = (const float*)d_in[6];
    const float* b3 = (const float*)d_in[7];
    float* out = (float*)d_out;

    int n_nodes = in_sizes[0] / INDIM;
    if (n_nodes > MAX_NODES) n_nodes = MAX_NODES;
    int E = out_size;

    int gblocks = (n_nodes + 127) / 128;
    precompute_kernel<<<gblocks, 256>>>(z, W1, b1, n_nodes);
    edge_kernel<<<296, 256>>>(ei, W2, b2, W3, b3, out, E);
}

// round 6
// speedup vs baseline: 1.5541x; 1.0833x over previous
#include <cuda_runtime.h>

#define MAX_NODES 100000
#define INDIM 128
#define HID 64

typedef unsigned long long u64;

// Scratch: per-node projections P[n][0:64]=z@W1a + b1, P[n][64:128]=z@W1b
__device__ float g_P[MAX_NODES * 128];

// ---------------------------------------------------------------------------
// f32x2 packed helpers (Blackwell — ptxas won't auto-fuse, PTX only)
__device__ __forceinline__ u64 pack2(float lo, float hi) {
    u64 r;
    asm("mov.b64 %0, {%1, %2};" : "=l"(r) : "f"(lo), "f"(hi));
    return r;
}
__device__ __forceinline__ void unpack2(u64 v, float& lo, float& hi) {
    asm("mov.b64 {%0, %1}, %2;" : "=f"(lo), "=f"(hi) : "l"(v));
}
__device__ __forceinline__ void ffma2(u64& d, u64 a, u64 b) {
    asm("fma.rn.f32x2 %0, %1, %2, %0;" : "+l"(d) : "l"(a), "l"(b));
}
__device__ __forceinline__ u64 fadd2(u64 a, u64 b) {
    u64 r;
    asm("add.rn.f32x2 %0, %1, %2;" : "=l"(r) : "l"(a), "l"(b));
    return r;
}

// ---------------------------------------------------------------------------
// Precompute GEMM: P[100K,128] = z[100K,128] @ Wcat[128,128]  (+ b1 on cols 0..63)
__global__ __launch_bounds__(256) void precompute_kernel(
    const float* __restrict__ z, const float* __restrict__ W1,
    const float* __restrict__ b1, int n_nodes)
{
    __shared__ __align__(16) float zs[32 * 132];
    __shared__ __align__(16) float ws[32 * 128];

    const int tid = threadIdx.x;
    const int g   = tid >> 4;
    const int c   = tid & 15;
    const int c0  = c * 8;
    const int nb  = blockIdx.x * 128;

    u64 acc2[8][4];
#pragma unroll
    for (int i = 0; i < 8; i++)
#pragma unroll
        for (int j = 0; j < 4; j++) acc2[i][j] = 0ull;

    for (int kc = 0; kc < 4; kc++) {
        __syncthreads();
        for (int idx = tid; idx < 128 * 32; idx += 256) {
            int n  = idx >> 5;
            int kq = idx & 31;
            int row = nb + n;
            float v = (row < n_nodes) ? z[(size_t)row * 128 + kc * 32 + kq] : 0.f;
            zs[kq * 132 + n] = v;
        }
        for (int idx = tid; idx < 32 * 128; idx += 256) {
            int kl = idx >> 7;
            int o  = idx & 127;
            int kk = kc * 32 + kl;
            float wv = (o < 64) ? W1[kk * 64 + o] : W1[(128 + kk) * 64 + (o - 64)];
            ws[idx] = wv;
        }
        __syncthreads();

#pragma unroll
        for (int k = 0; k < 32; k++) {
            float4 a0 = *(const float4*)&zs[k * 132 + g * 8];
            float4 a1 = *(const float4*)&zs[k * 132 + g * 8 + 4];
            ulonglong2 bv0 = *(const ulonglong2*)&ws[k * 128 + c0];
            ulonglong2 bv1 = *(const ulonglong2*)&ws[k * 128 + c0 + 4];
            float a[8] = {a0.x, a0.y, a0.z, a0.w, a1.x, a1.y, a1.z, a1.w};
#pragma unroll
            for (int i = 0; i < 8; i++) {
                u64 ad = pack2(a[i], a[i]);
                ffma2(acc2[i][0], ad, bv0.x);
                ffma2(acc2[i][1], ad, bv0.y);
                ffma2(acc2[i][2], ad, bv1.x);
                ffma2(acc2[i][3], ad, bv1.y);
            }
        }
    }

    float bias[8];
#pragma unroll
    for (int j = 0; j < 8; j++) bias[j] = (c0 < 64) ? b1[c0 + j] : 0.f;

#pragma unroll
    for (int i = 0; i < 8; i++) {
        int row = nb + g * 8 + i;
        if (row < n_nodes) {
            float v[8];
#pragma unroll
            for (int j = 0; j < 4; j++) unpack2(acc2[i][j], v[2 * j], v[2 * j + 1]);
            float4 o0 = make_float4(v[0] + bias[0], v[1] + bias[1],
                                    v[2] + bias[2], v[3] + bias[3]);
            float4 o1 = make_float4(v[4] + bias[4], v[5] + bias[5],
                                    v[6] + bias[6], v[7] + bias[7]);
            *(float4*)&g_P[(size_t)row * 128 + c0]     = o0;
            *(float4*)&g_P[(size_t)row * 128 + c0 + 4] = o1;
        }
    }
}

// ---------------------------------------------------------------------------
// Edge kernel: warp processes batches of 32 edges, in 8 groups of 4.
//  - gather: lane = feature pair; group-of-4 P rows prefetched one group ahead
//  - h1 staged via double-buffered smem (1 syncwarp per 4 edges)
//  - layer2: lane = neuron, W2 column in 32 f32x2 regs; 2 edges processed
//    jointly (8 independent accumulator chains) for ILP
//  - layer3: after 32 edges, lane e reduces its own edge in-lane (no shfl)
__global__ __launch_bounds__(256, 2) void edge_kernel(
    const void* __restrict__ eidx,
    const float* __restrict__ W2, const float* __restrict__ b2,
    const float* __restrict__ W3, const float* __restrict__ b3,
    float* __restrict__ out, int E)
{
    __shared__ __align__(16) u64   h1s[8][2][4][32];  // [warp][buf][edge-in-grp][pair]
    __shared__ __align__(16) float h2s[8][32][36];    // [warp][edge][neuron]
    __shared__ __align__(16) float w3s[32];

    const int lane = threadIdx.x & 31;
    const int wid  = threadIdx.x >> 5;
    const int gw   = (blockIdx.x * blockDim.x + threadIdx.x) >> 5;
    const int GW   = (gridDim.x * blockDim.x) >> 5;
    const int STRIDE = GW * 32;

    if (threadIdx.x < 32) w3s[threadIdx.x] = W3[threadIdx.x];

    // int64 vs int32 edge_index detection: LE int64 < 100000 -> odd words zero
    const int* ei32 = (const int*)eidx;
    int oddw = ei32[2 * lane + 1] | ei32[2 * lane + 65];
    const bool is64 = (__ballot_sync(0xffffffffu, oddw != 0) == 0u);

    // per-lane W2 column packed along k (lane = output neuron)
    u64 w2p[32];
#pragma unroll
    for (int k2 = 0; k2 < 32; k2++)
        w2p[k2] = pack2(W2[(2 * k2) * 32 + lane], W2[(2 * k2 + 1) * 32 + lane]);
    const float b2r = b2[lane];
    const float b3v = b3[0];

    const char* __restrict__ Pb = (const char*)g_P;
    const unsigned lane8 = (unsigned)lane * 8u;
    const int Em1 = E - 1;

    __syncthreads();  // w3s visible

    for (int b = gw * 32; b < E; b += STRIDE) {
        // coalesced batch index load (clamped)
        int me = min(b + lane, Em1);
        int iL, jL;
        if (is64) {
            iL = (int)((const long long*)eidx)[me];
            jL = (int)((const long long*)eidx)[(long long)E + me];
        } else {
            iL = ((const int*)eidx)[me];
            jL = ((const int*)eidx)[E + me];
        }

        // prologue: P rows for group 0 (edges 0..3)
        u64 pa[4], pb[4];
#pragma unroll
        for (int t = 0; t < 4; t++) {
            int ii = __shfl_sync(0xffffffffu, iL, t);
            int jj = __shfl_sync(0xffffffffu, jL, t);
            pa[t] = *(const u64*)(Pb + (unsigned)ii * 512u + lane8);
            pb[t] = *(const u64*)(Pb + (unsigned)jj * 512u + 256u + lane8);
        }

#pragma unroll 2
        for (int g = 0; g < 8; g++) {
            const int buf = g & 1;

            // layer 1 for current group: packed add + relu, store to smem
#pragma unroll
            for (int t = 0; t < 4; t++) {
                float hx, hy;
                unpack2(fadd2(pa[t], pb[t]), hx, hy);
                h1s[wid][buf][t][lane] = pack2(fmaxf(hx, 0.f), fmaxf(hy, 0.f));
            }
            __syncwarp();

            // issue P loads for next group (consumed next iteration)
            u64 npa[4], npb[4];
#pragma unroll
            for (int t = 0; t < 4; t++) { npa[t] = pa[t]; npb[t] = pb[t]; }
            if (g < 7) {
#pragma unroll
                for (int t = 0; t < 4; t++) {
                    int en = (g + 1) * 4 + t;
                    int ii = __shfl_sync(0xffffffffu, iL, en);
                    int jj = __shfl_sync(0xffffffffu, jL, en);
                    npa[t] = *(const u64*)(Pb + (unsigned)ii * 512u + lane8);
                    npb[t] = *(const u64*)(Pb + (unsigned)jj * 512u + 256u + lane8);
                }
            }

            // layer 2: edges processed in pairs (8 independent chains)
#pragma unroll
            for (int tp = 0; tp < 4; tp += 2) {
                u64 aA0 = pack2(b2r, 0.f), aA1 = 0ull, aA2 = 0ull, aA3 = 0ull;
                u64 aB0 = pack2(b2r, 0.f), aB1 = 0ull, aB2 = 0ull, aB3 = 0ull;
                const ulonglong2* hqA = (const ulonglong2*)h1s[wid][buf][tp];
                const ulonglong2* hqB = (const ulonglong2*)h1s[wid][buf][tp + 1];
#pragma unroll
                for (int k = 0; k < 8; k++) {
                    ulonglong2 hA0 = hqA[2 * k];
                    ulonglong2 hA1 = hqA[2 * k + 1];
                    ulonglong2 hB0 = hqB[2 * k];
                    ulonglong2 hB1 = hqB[2 * k + 1];
                    ffma2(aA0, hA0.x, w2p[4 * k + 0]);
                    ffma2(aB0, hB0.x, w2p[4 * k + 0]);
                    ffma2(aA1, hA0.y, w2p[4 * k + 1]);
                    ffma2(aB1, hB0.y, w2p[4 * k + 1]);
                    ffma2(aA2, hA1.x, w2p[4 * k + 2]);
                    ffma2(aB2, hB1.x, w2p[4 * k + 2]);
                    ffma2(aA3, hA1.y, w2p[4 * k + 3]);
                    ffma2(aB3, hB1.y, w2p[4 * k + 3]);
                }
                aA0 = fadd2(fadd2(aA0, aA1), fadd2(aA2, aA3));
                aB0 = fadd2(fadd2(aB0, aB1), fadd2(aB2, aB3));
                float Alo, Ahi, Blo, Bhi;
                unpack2(aA0, Alo, Ahi);
                unpack2(aB0, Blo, Bhi);
                h2s[wid][g * 4 + tp][lane]     = fmaxf(Alo + Ahi, 0.f);
                h2s[wid][g * 4 + tp + 1][lane] = fmaxf(Blo + Bhi, 0.f);
            }

#pragma unroll
            for (int t = 0; t < 4; t++) { pa[t] = npa[t]; pb[t] = npb[t]; }
        }
        __syncwarp();

        // layer 3: lane handles edge b+lane entirely in-lane
        {
            const ulonglong2* hrow = (const ulonglong2*)&h2s[wid][lane][0];
            const ulonglong2* w3p  = (const ulonglong2*)w3s;
            u64 c0 = 0ull, c1 = 0ull, c2 = 0ull, c3 = 0ull;
#pragma unroll
            for (int q = 0; q < 4; q++) {
                ulonglong2 h = hrow[2 * q];
                ulonglong2 g2 = hrow[2 * q + 1];
                ulonglong2 w = w3p[2 * q];
                ulonglong2 v = w3p[2 * q + 1];
                ffma2(c0, h.x, w.x);
                ffma2(c1, h.y, w.y);
                ffma2(c2, g2.x, v.x);
                ffma2(c3, g2.y, v.y);
            }
            c0 = fadd2(fadd2(c0, c1), fadd2(c2, c3));
            float lo, hi;
            unpack2(c0, lo, hi);
            float logit = lo + hi + b3v;
            float sig = __fdividef(1.f, 1.f + __expf(-logit));
            if (b + lane < E) out[b + lane] = sig;
        }
        __syncwarp();
    }
}

// ---------------------------------------------------------------------------
extern "C" void kernel_launch(void* const* d_in, const int* in_sizes, int n_in,
                              void* d_out, int out_size)
{
    const float* z  = (const float*)d_in[0];
    const void*  ei = d_in[1];
    const float* W1 = (const float*)d_in[2];
    const float* b1 = (const float*)d_in[3];
    const float* W2 = (const float*)d_in[4];
    const float* b2 = (const float*)d_in[5];
    const float* W3 = (const float*)d_in[6];
    const float* b3 = (const float*)d_in[7];
    float* out = (float*)d_out;

    int n_nodes = in_sizes[0] / INDIM;
    if (n_nodes > MAX_NODES) n_nodes = MAX_NODES;
    int E = out_size;

    int gblocks = (n_nodes + 127) / 128;
    precompute_kernel<<<gblocks, 256>>>(z, W1, b1, n_nodes);
    edge_kernel<<<296, 256>>>(ei, W2, b2, W3, b3, out, E);
}

// round 7
// speedup vs baseline: 1.7320x; 1.1145x over previous
#include <cuda_runtime.h>

#define MAX_NODES 100000
#define INDIM 128
#define HID 64

typedef unsigned long long u64;

// Scratch: per-node projections P[n][0:64]=z@W1a + b1, P[n][64:128]=z@W1b
__device__ float g_P[MAX_NODES * 128];

// ---------------------------------------------------------------------------
// f32x2 packed helpers (Blackwell — ptxas won't auto-fuse, PTX only)
__device__ __forceinline__ u64 pack2(float lo, float hi) {
    u64 r;
    asm("mov.b64 %0, {%1, %2};" : "=l"(r) : "f"(lo), "f"(hi));
    return r;
}
__device__ __forceinline__ void unpack2(u64 v, float& lo, float& hi) {
    asm("mov.b64 {%0, %1}, %2;" : "=f"(lo), "=f"(hi) : "l"(v));
}
__device__ __forceinline__ void ffma2(u64& d, u64 a, u64 b) {
    asm("fma.rn.f32x2 %0, %1, %2, %0;" : "+l"(d) : "l"(a), "l"(b));
}
__device__ __forceinline__ u64 fadd2(u64 a, u64 b) {
    u64 r;
    asm("add.rn.f32x2 %0, %1, %2;" : "=l"(r) : "l"(a), "l"(b));
    return r;
}

// ---------------------------------------------------------------------------
// Precompute GEMM: P[100K,128] = z[100K,128] @ Wcat[128,128]  (+ b1 on cols 0..63)
__global__ __launch_bounds__(256) void precompute_kernel(
    const float* __restrict__ z, const float* __restrict__ W1,
    const float* __restrict__ b1, int n_nodes)
{
    __shared__ __align__(16) float zs[32 * 132];
    __shared__ __align__(16) float ws[32 * 128];

    const int tid = threadIdx.x;
    const int g   = tid >> 4;
    const int c   = tid & 15;
    const int c0  = c * 8;
    const int nb  = blockIdx.x * 128;

    u64 acc2[8][4];
#pragma unroll
    for (int i = 0; i < 8; i++)
#pragma unroll
        for (int j = 0; j < 4; j++) acc2[i][j] = 0ull;

    for (int kc = 0; kc < 4; kc++) {
        __syncthreads();
        for (int idx = tid; idx < 128 * 32; idx += 256) {
            int n  = idx >> 5;
            int kq = idx & 31;
            int row = nb + n;
            float v = (row < n_nodes) ? z[(size_t)row * 128 + kc * 32 + kq] : 0.f;
            zs[kq * 132 + n] = v;
        }
        for (int idx = tid; idx < 32 * 128; idx += 256) {
            int kl = idx >> 7;
            int o  = idx & 127;
            int kk = kc * 32 + kl;
            float wv = (o < 64) ? W1[kk * 64 + o] : W1[(128 + kk) * 64 + (o - 64)];
            ws[idx] = wv;
        }
        __syncthreads();

#pragma unroll
        for (int k = 0; k < 32; k++) {
            float4 a0 = *(const float4*)&zs[k * 132 + g * 8];
            float4 a1 = *(const float4*)&zs[k * 132 + g * 8 + 4];
            ulonglong2 bv0 = *(const ulonglong2*)&ws[k * 128 + c0];
            ulonglong2 bv1 = *(const ulonglong2*)&ws[k * 128 + c0 + 4];
            float a[8] = {a0.x, a0.y, a0.z, a0.w, a1.x, a1.y, a1.z, a1.w};
#pragma unroll
            for (int i = 0; i < 8; i++) {
                u64 ad = pack2(a[i], a[i]);
                ffma2(acc2[i][0], ad, bv0.x);
                ffma2(acc2[i][1], ad, bv0.y);
                ffma2(acc2[i][2], ad, bv1.x);
                ffma2(acc2[i][3], ad, bv1.y);
            }
        }
    }

    float bias[8];
#pragma unroll
    for (int j = 0; j < 8; j++) bias[j] = (c0 < 64) ? b1[c0 + j] : 0.f;

#pragma unroll
    for (int i = 0; i < 8; i++) {
        int row = nb + g * 8 + i;
        if (row < n_nodes) {
            float v[8];
#pragma unroll
            for (int j = 0; j < 4; j++) unpack2(acc2[i][j], v[2 * j], v[2 * j + 1]);
            float4 o0 = make_float4(v[0] + bias[0], v[1] + bias[1],
                                    v[2] + bias[2], v[3] + bias[3]);
            float4 o1 = make_float4(v[4] + bias[4], v[5] + bias[5],
                                    v[6] + bias[6], v[7] + bias[7]);
            *(float4*)&g_P[(size_t)row * 128 + c0]     = o0;
            *(float4*)&g_P[(size_t)row * 128 + c0 + 4] = o1;
        }
    }
}

// ---------------------------------------------------------------------------
// Edge kernel: warp processes 32-edge batches as a register-tiled GEMM.
// Phase 1: gather P rows (lane=k-pair, coalesced) + layer1 add/relu ->
//          h1u[e][k2] u64 (row-major, pad 33, conflict-free).
// Phase 2: 32x32x64 GEMM: lane tile 4 edges x 8 neurons, k-parity packed
//          FFMA2 accumulators; W2 pair table bank-interleaved in smem.
// Phase 3: per-lane dot with w3 slice, 4-lane bfly reduce, sigmoid,
//          float4-coalesced store. No h2 smem, no 32-wide reductions.
__global__ __launch_bounds__(256, 2) void edge_kernel(
    const void* __restrict__ eidx,
    const float* __restrict__ W2, const float* __restrict__ b2,
    const float* __restrict__ W3, const float* __restrict__ b3,
    float* __restrict__ out, int E)
{
    __shared__ __align__(16) u64 h1u[8][32][33];        // [warp][edge][k-pair], 67.6KB
    __shared__ __align__(16) ulonglong2 w2i[512];       // [k2][chunk][ng] interleaved, 8KB
    __shared__ float w3s[32];
    __shared__ float b2sm[32];

    const int lane = threadIdx.x & 31;
    const int wid  = threadIdx.x >> 5;
    const int eg   = lane >> 2;     // edge group 0..7 -> edges eg*4..eg*4+3
    const int ng   = lane & 3;      // neuron group 0..3 -> neurons ng*8..ng*8+7
    const int gw   = (blockIdx.x * blockDim.x + threadIdx.x) >> 5;
    const int GW   = (gridDim.x * blockDim.x) >> 5;
    const int STRIDE = GW * 32;

    // Build bank-interleaved W2 k-pair table + small vectors (once per block).
    // w2i[(k2*4 + c)*4 + ng] = { (W2[2k2][n0], W2[2k2+1][n0]),
    //                            (W2[2k2][n0+1], W2[2k2+1][n0+1]) }, n0 = ng*8+2c
    for (int id = threadIdx.x; id < 512; id += 256) {
        int k2 = id >> 4;
        int c  = (id >> 2) & 3;
        int g2 = id & 3;
        int n0 = g2 * 8 + 2 * c;
        ulonglong2 v;
        v.x = pack2(W2[(2 * k2) * 32 + n0],     W2[(2 * k2 + 1) * 32 + n0]);
        v.y = pack2(W2[(2 * k2) * 32 + n0 + 1], W2[(2 * k2 + 1) * 32 + n0 + 1]);
        w2i[id] = v;
    }
    if (threadIdx.x < 32) {
        w3s[threadIdx.x]  = W3[threadIdx.x];
        b2sm[threadIdx.x] = b2[threadIdx.x];
    }
    const float b3v = b3[0];

    // int64 vs int32 edge_index detection: LE int64 < 100000 -> odd words zero
    const int* ei32 = (const int*)eidx;
    int oddw = ei32[2 * lane + 1] | ei32[2 * lane + 65];
    const bool is64 = (__ballot_sync(0xffffffffu, oddw != 0) == 0u);

    const char* __restrict__ Pb = (const char*)g_P;
    const unsigned lane8 = (unsigned)lane * 8u;
    const int Em1 = E - 1;

    __syncthreads();  // w2i/w3s/b2sm visible

    u64* __restrict__ h1w = &h1u[wid][0][0];

    for (int b = gw * 32; b < E; b += STRIDE) {
        // ---- coalesced batch index load (clamped) ----
        int me = min(b + lane, Em1);
        int iL, jL;
        if (is64) {
            iL = (int)((const long long*)eidx)[me];
            jL = (int)((const long long*)eidx)[(long long)E + me];
        } else {
            iL = ((const int*)eidx)[me];
            jL = ((const int*)eidx)[E + me];
        }

        // ---- phase 1: gather + layer1, groups of 4 with 1-group prefetch ----
        u64 pa[4], pb[4];
#pragma unroll
        for (int t = 0; t < 4; t++) {
            int ii = __shfl_sync(0xffffffffu, iL, t);
            int jj = __shfl_sync(0xffffffffu, jL, t);
            pa[t] = *(const u64*)(Pb + (unsigned)ii * 512u + lane8);
            pb[t] = *(const u64*)(Pb + (unsigned)jj * 512u + 256u + lane8);
        }
#pragma unroll
        for (int g = 0; g < 8; g++) {
            u64 npa[4], npb[4];
            if (g < 7) {
#pragma unroll
                for (int t = 0; t < 4; t++) {
                    int en = (g + 1) * 4 + t;
                    int ii = __shfl_sync(0xffffffffu, iL, en);
                    int jj = __shfl_sync(0xffffffffu, jL, en);
                    npa[t] = *(const u64*)(Pb + (unsigned)ii * 512u + lane8);
                    npb[t] = *(const u64*)(Pb + (unsigned)jj * 512u + 256u + lane8);
                }
            }
#pragma unroll
            for (int t = 0; t < 4; t++) {
                float hx, hy;
                unpack2(fadd2(pa[t], pb[t]), hx, hy);
                h1w[(g * 4 + t) * 33 + lane] = pack2(fmaxf(hx, 0.f), fmaxf(hy, 0.f));
            }
            if (g < 7) {
#pragma unroll
                for (int t = 0; t < 4; t++) { pa[t] = npa[t]; pb[t] = npb[t]; }
            }
        }
        __syncwarp();

        // ---- phase 2: 32x32x64 GEMM, lane tile 4e x 8n, k-parity FFMA2 ----
        u64 acc[4][8];
#pragma unroll
        for (int e = 0; e < 4; e++)
#pragma unroll
            for (int n = 0; n < 8; n++) acc[e][n] = 0ull;

        const int e0 = eg * 4;
#pragma unroll 2
        for (int k2 = 0; k2 < 32; k2++) {
            u64 a0 = h1w[(e0 + 0) * 33 + k2];
            u64 a1 = h1w[(e0 + 1) * 33 + k2];
            u64 a2 = h1w[(e0 + 2) * 33 + k2];
            u64 a3 = h1w[(e0 + 3) * 33 + k2];
            ulonglong2 w0 = w2i[(k2 << 4) + 0  + ng];
            ulonglong2 w1 = w2i[(k2 << 4) + 4  + ng];
            ulonglong2 w2v = w2i[(k2 << 4) + 8  + ng];
            ulonglong2 w3v = w2i[(k2 << 4) + 12 + ng];
            ffma2(acc[0][0], a0, w0.x);  ffma2(acc[0][1], a0, w0.y);
            ffma2(acc[1][0], a1, w0.x);  ffma2(acc[1][1], a1, w0.y);
            ffma2(acc[2][0], a2, w0.x);  ffma2(acc[2][1], a2, w0.y);
            ffma2(acc[3][0], a3, w0.x);  ffma2(acc[3][1], a3, w0.y);
            ffma2(acc[0][2], a0, w1.x);  ffma2(acc[0][3], a0, w1.y);
            ffma2(acc[1][2], a1, w1.x);  ffma2(acc[1][3], a1, w1.y);
            ffma2(acc[2][2], a2, w1.x);  ffma2(acc[2][3], a2, w1.y);
            ffma2(acc[3][2], a3, w1.x);  ffma2(acc[3][3], a3, w1.y);
            ffma2(acc[0][4], a0, w2v.x); ffma2(acc[0][5], a0, w2v.y);
            ffma2(acc[1][4], a1, w2v.x); ffma2(acc[1][5], a1, w2v.y);
            ffma2(acc[2][4], a2, w2v.x); ffma2(acc[2][5], a2, w2v.y);
            ffma2(acc[3][4], a3, w2v.x); ffma2(acc[3][5], a3, w2v.y);
            ffma2(acc[0][6], a0, w3v.x); ffma2(acc[0][7], a0, w3v.y);
            ffma2(acc[1][6], a1, w3v.x); ffma2(acc[1][7], a1, w3v.y);
            ffma2(acc[2][6], a2, w3v.x); ffma2(acc[2][7], a2, w3v.y);
            ffma2(acc[3][6], a3, w3v.x); ffma2(acc[3][7], a3, w3v.y);
        }

        // ---- phase 3: bias+relu, dot with w3 slice, 4-lane reduce, store ----
        float b2q[8], w3q[8];
#pragma unroll
        for (int q = 0; q < 8; q++) {
            b2q[q] = b2sm[ng * 8 + q];
            w3q[q] = w3s[ng * 8 + q];
        }
        float part[4];
#pragma unroll
        for (int e = 0; e < 4; e++) {
            float p = 0.f;
#pragma unroll
            for (int n = 0; n < 8; n++) {
                float lo, hi;
                unpack2(acc[e][n], lo, hi);
                float h = fmaxf(lo + hi + b2q[n], 0.f);
                p = fmaf(h, w3q[n], p);
            }
            part[e] = p;
        }
#pragma unroll
        for (int e = 0; e < 4; e++) {
            part[e] += __shfl_xor_sync(0xffffffffu, part[e], 1);
            part[e] += __shfl_xor_sync(0xffffffffu, part[e], 2);
        }
        if (ng == 0) {
            float sig[4];
#pragma unroll
            for (int t = 0; t < 4; t++)
                sig[t] = __fdividef(1.f, 1.f + __expf(-(part[t] + b3v)));
            int ob = b + e0;
            if (ob + 3 < E) {
                *(float4*)(out + ob) = make_float4(sig[0], sig[1], sig[2], sig[3]);
            } else {
#pragma unroll
                for (int t = 0; t < 4; t++)
                    if (ob + t < E) out[ob + t] = sig[t];
            }
        }
        __syncwarp();  // protect h1u before next batch overwrites
    }
}

// ---------------------------------------------------------------------------
extern "C" void kernel_launch(void* const* d_in, const int* in_sizes, int n_in,
                              void* d_out, int out_size)
{
    const float* z  = (const float*)d_in[0];
    const void*  ei = d_in[1];
    const float* W1 = (const float*)d_in[2];
    const float* b1 = (const float*)d_in[3];
    const float* W2 = (const float*)d_in[4];
    const float* b2 = (const float*)d_in[5];
    const float* W3 = (const float*)d_in[6];
    const float* b3 = (const float*)d_in[7];
    float* out = (float*)d_out;

    int n_nodes = in_sizes[0] / INDIM;
    if (n_nodes > MAX_NODES) n_nodes = MAX_NODES;
    int E = out_size;

    int gblocks = (n_nodes + 127) / 128;
    precompute_kernel<<<gblocks, 256>>>(z, W1, b1, n_nodes);
    edge_kernel<<<296, 256>>>(ei, W2, b2, W3, b3, out, E);
}

// round 8
// speedup vs baseline: 1.7363x; 1.0025x over previous
#include <cuda_runtime.h>

#define MAX_NODES 100000
#define INDIM 128
#define HID 64

typedef unsigned long long u64;

// Scratch: per-node projections P[n][0:64]=z@W1a + b1, P[n][64:128]=z@W1b
__device__ float g_P[MAX_NODES * 128];

// ---------------------------------------------------------------------------
// f32x2 packed helpers (Blackwell — ptxas won't auto-fuse, PTX only)
__device__ __forceinline__ u64 pack2(float lo, float hi) {
    u64 r;
    asm("mov.b64 %0, {%1, %2};" : "=l"(r) : "f"(lo), "f"(hi));
    return r;
}
__device__ __forceinline__ void unpack2(u64 v, float& lo, float& hi) {
    asm("mov.b64 {%0, %1}, %2;" : "=f"(lo), "=f"(hi) : "l"(v));
}
__device__ __forceinline__ void ffma2(u64& d, u64 a, u64 b) {
    asm("fma.rn.f32x2 %0, %1, %2, %0;" : "+l"(d) : "l"(a), "l"(b));
}
__device__ __forceinline__ u64 fadd2(u64 a, u64 b) {
    u64 r;
    asm("add.rn.f32x2 %0, %1, %2;" : "=l"(r) : "l"(a), "l"(b));
    return r;
}

// ---------------------------------------------------------------------------
// Precompute GEMM: P[100K,128] = z[100K,128] @ Wcat[128,128]  (+ b1 on cols 0..63)
// z chunk stored transposed AND pre-duplicated as (v,v) u64 pairs so the
// A fragment is a direct FFMA2 operand (no per-k MOV duplication).
#define ZS_STRIDE 134  // u64 stride: even (16B-aligned rows), mod16=6 (4-way STS)
__global__ __launch_bounds__(256) void precompute_kernel(
    const float* __restrict__ z, const float* __restrict__ W1,
    const float* __restrict__ b1, int n_nodes)
{
    __shared__ __align__(16) u64   zs2[32 * ZS_STRIDE];  // [k][node] dup pairs
    __shared__ __align__(16) float ws[32 * 128];         // [k][col]

    const int tid = threadIdx.x;
    const int g   = tid >> 4;
    const int c   = tid & 15;
    const int c0  = c * 8;
    const int nb  = blockIdx.x * 128;

    u64 acc2[8][4];
#pragma unroll
    for (int i = 0; i < 8; i++)
#pragma unroll
        for (int j = 0; j < 4; j++) acc2[i][j] = 0ull;

    for (int kc = 0; kc < 4; kc++) {
        __syncthreads();
        for (int idx = tid; idx < 128 * 32; idx += 256) {
            int n  = idx >> 5;
            int kq = idx & 31;
            int row = nb + n;
            float v = (row < n_nodes) ? z[(size_t)row * 128 + kc * 32 + kq] : 0.f;
            zs2[kq * ZS_STRIDE + n] = pack2(v, v);
        }
        for (int idx = tid; idx < 32 * 128; idx += 256) {
            int kl = idx >> 7;
            int o  = idx & 127;
            int kk = kc * 32 + kl;
            float wv = (o < 64) ? W1[kk * 64 + o] : W1[(128 + kk) * 64 + (o - 64)];
            ws[idx] = wv;
        }
        __syncthreads();

#pragma unroll
        for (int k = 0; k < 32; k++) {
            const u64* zrow = &zs2[k * ZS_STRIDE + g * 8];
            ulonglong2 za0 = *(const ulonglong2*)(zrow + 0);
            ulonglong2 za1 = *(const ulonglong2*)(zrow + 2);
            ulonglong2 za2 = *(const ulonglong2*)(zrow + 4);
            ulonglong2 za3 = *(const ulonglong2*)(zrow + 6);
            ulonglong2 bv0 = *(const ulonglong2*)&ws[k * 128 + c0];
            ulonglong2 bv1 = *(const ulonglong2*)&ws[k * 128 + c0 + 4];
            u64 ad[8] = {za0.x, za0.y, za1.x, za1.y, za2.x, za2.y, za3.x, za3.y};
#pragma unroll
            for (int i = 0; i < 8; i++) {
                ffma2(acc2[i][0], ad[i], bv0.x);
                ffma2(acc2[i][1], ad[i], bv0.y);
                ffma2(acc2[i][2], ad[i], bv1.x);
                ffma2(acc2[i][3], ad[i], bv1.y);
            }
        }
    }

    float bias[8];
#pragma unroll
    for (int j = 0; j < 8; j++) bias[j] = (c0 < 64) ? b1[c0 + j] : 0.f;

#pragma unroll
    for (int i = 0; i < 8; i++) {
        int row = nb + g * 8 + i;
        if (row < n_nodes) {
            float v[8];
#pragma unroll
            for (int j = 0; j < 4; j++) unpack2(acc2[i][j], v[2 * j], v[2 * j + 1]);
            float4 o0 = make_float4(v[0] + bias[0], v[1] + bias[1],
                                    v[2] + bias[2], v[3] + bias[3]);
            float4 o1 = make_float4(v[4] + bias[4], v[5] + bias[5],
                                    v[6] + bias[6], v[7] + bias[7]);
            *(float4*)&g_P[(size_t)row * 128 + c0]     = o0;
            *(float4*)&g_P[(size_t)row * 128 + c0 + 4] = o1;
        }
    }
}

// ---------------------------------------------------------------------------
// Edge kernel: warp processes 32-edge batches as a register-tiled GEMM.
// h1 stored stride-32 u64 rows with XOR swizzle col' = k2 ^ ((e>>2)<<1):
//  - writes: permutation of lanes -> conflict-free STS.64
//  - reads: LDS.128 per edge covers 2 k-pairs; 8 egs hit 16 distinct u64
//    slots -> single-wavefront, conflict-free.
__global__ __launch_bounds__(256, 2) void edge_kernel(
    const void* __restrict__ eidx,
    const float* __restrict__ W2, const float* __restrict__ b2,
    const float* __restrict__ W3, const float* __restrict__ b3,
    float* __restrict__ out, int E)
{
    __shared__ __align__(16) u64 h1u[8 * 32 * 32];      // [warp][edge][k-pair sw], 64KB
    __shared__ __align__(16) ulonglong2 w2i[512];       // [k2][chunk][ng] interleaved, 8KB
    __shared__ float w3s[32];
    __shared__ float b2sm[32];

    const int lane = threadIdx.x & 31;
    const int wid  = threadIdx.x >> 5;
    const int eg   = lane >> 2;     // edge group 0..7 -> edges eg*4..eg*4+3
    const int ng   = lane & 3;      // neuron group 0..3 -> neurons ng*8..ng*8+7
    const int gw   = (blockIdx.x * blockDim.x + threadIdx.x) >> 5;
    const int GW   = (gridDim.x * blockDim.x) >> 5;
    const int STRIDE = GW * 32;

    // Bank-interleaved W2 k-pair table:
    // w2i[(k2*4 + c)*4 + ng] = pairs for neurons (ng*8+2c, ng*8+2c+1) at k-pair k2
    for (int id = threadIdx.x; id < 512; id += 256) {
        int k2 = id >> 4;
        int c  = (id >> 2) & 3;
        int g2 = id & 3;
        int n0 = g2 * 8 + 2 * c;
        ulonglong2 v;
        v.x = pack2(W2[(2 * k2) * 32 + n0],     W2[(2 * k2 + 1) * 32 + n0]);
        v.y = pack2(W2[(2 * k2) * 32 + n0 + 1], W2[(2 * k2 + 1) * 32 + n0 + 1]);
        w2i[id] = v;
    }
    if (threadIdx.x < 32) {
        w3s[threadIdx.x]  = W3[threadIdx.x];
        b2sm[threadIdx.x] = b2[threadIdx.x];
    }
    const float b3v = b3[0];

    // int64 vs int32 edge_index detection: LE int64 < 100000 -> odd words zero
    const int* ei32 = (const int*)eidx;
    int oddw = ei32[2 * lane + 1] | ei32[2 * lane + 65];
    const bool is64 = (__ballot_sync(0xffffffffu, oddw != 0) == 0u);

    const char* __restrict__ Pb = (const char*)g_P;
    const unsigned lane8 = (unsigned)lane * 8u;
    const int Em1 = E - 1;

    __syncthreads();  // w2i/w3s/b2sm visible

    u64* __restrict__ h1w = &h1u[wid * 1024];

    for (int b = gw * 32; b < E; b += STRIDE) {
        // ---- coalesced batch index load (clamped) ----
        int me = min(b + lane, Em1);
        int iL, jL;
        if (is64) {
            iL = (int)((const long long*)eidx)[me];
            jL = (int)((const long long*)eidx)[(long long)E + me];
        } else {
            iL = ((const int*)eidx)[me];
            jL = ((const int*)eidx)[E + me];
        }

        // ---- phase 1: gather + layer1, groups of 4 with 1-group prefetch ----
        u64 pa[4], pb[4];
#pragma unroll
        for (int t = 0; t < 4; t++) {
            int ii = __shfl_sync(0xffffffffu, iL, t);
            int jj = __shfl_sync(0xffffffffu, jL, t);
            pa[t] = *(const u64*)(Pb + (unsigned)ii * 512u + lane8);
            pb[t] = *(const u64*)(Pb + (unsigned)jj * 512u + 256u + lane8);
        }
#pragma unroll
        for (int g = 0; g < 8; g++) {
            u64 npa[4], npb[4];
            if (g < 7) {
#pragma unroll
                for (int t = 0; t < 4; t++) {
                    int en = (g + 1) * 4 + t;
                    int ii = __shfl_sync(0xffffffffu, iL, en);
                    int jj = __shfl_sync(0xffffffffu, jL, en);
                    npa[t] = *(const u64*)(Pb + (unsigned)ii * 512u + lane8);
                    npb[t] = *(const u64*)(Pb + (unsigned)jj * 512u + 256u + lane8);
                }
            }
            const int colw = lane ^ (g << 1);  // swizzle: edge group g
#pragma unroll
            for (int t = 0; t < 4; t++) {
                float hx, hy;
                unpack2(fadd2(pa[t], pb[t]), hx, hy);
                h1w[(g * 4 + t) * 32 + colw] = pack2(fmaxf(hx, 0.f), fmaxf(hy, 0.f));
            }
            if (g < 7) {
#pragma unroll
                for (int t = 0; t < 4; t++) { pa[t] = npa[t]; pb[t] = npb[t]; }
            }
        }
        __syncwarp();

        // ---- phase 2: 32x32x64 GEMM, lane tile 4e x 8n, 2 k-pairs/iter ----
        u64 acc[4][8];
#pragma unroll
        for (int e = 0; e < 4; e++)
#pragma unroll
            for (int n = 0; n < 8; n++) acc[e][n] = 0ull;

        const int e0  = eg * 4;
        const int egx = eg << 1;
#pragma unroll 4
        for (int k2 = 0; k2 < 32; k2 += 2) {
            const int col = k2 ^ egx;
            ulonglong2 A0 = *(const ulonglong2*)(h1w + (e0 + 0) * 32 + col);
            ulonglong2 A1 = *(const ulonglong2*)(h1w + (e0 + 1) * 32 + col);
            ulonglong2 A2 = *(const ulonglong2*)(h1w + (e0 + 2) * 32 + col);
            ulonglong2 A3 = *(const ulonglong2*)(h1w + (e0 + 3) * 32 + col);
            {   // k-pair k2 (A*.x)
                ulonglong2 w0  = w2i[(k2 << 4) + 0  + ng];
                ulonglong2 w1  = w2i[(k2 << 4) + 4  + ng];
                ulonglong2 w2v = w2i[(k2 << 4) + 8  + ng];
                ulonglong2 w3v = w2i[(k2 << 4) + 12 + ng];
                ffma2(acc[0][0], A0.x, w0.x);  ffma2(acc[0][1], A0.x, w0.y);
                ffma2(acc[1][0], A1.x, w0.x);  ffma2(acc[1][1], A1.x, w0.y);
                ffma2(acc[2][0], A2.x, w0.x);  ffma2(acc[2][1], A2.x, w0.y);
                ffma2(acc[3][0], A3.x, w0.x);  ffma2(acc[3][1], A3.x, w0.y);
                ffma2(acc[0][2], A0.x, w1.x);  ffma2(acc[0][3], A0.x, w1.y);
                ffma2(acc[1][2], A1.x, w1.x);  ffma2(acc[1][3], A1.x, w1.y);
                ffma2(acc[2][2], A2.x, w1.x);  ffma2(acc[2][3], A2.x, w1.y);
                ffma2(acc[3][2], A3.x, w1.x);  ffma2(acc[3][3], A3.x, w1.y);
                ffma2(acc[0][4], A0.x, w2v.x); ffma2(acc[0][5], A0.x, w2v.y);
                ffma2(acc[1][4], A1.x, w2v.x); ffma2(acc[1][5], A1.x, w2v.y);
                ffma2(acc[2][4], A2.x, w2v.x); ffma2(acc[2][5], A2.x, w2v.y);
                ffma2(acc[3][4], A3.x, w2v.x); ffma2(acc[3][5], A3.x, w2v.y);
                ffma2(acc[0][6], A0.x, w3v.x); ffma2(acc[0][7], A0.x, w3v.y);
                ffma2(acc[1][6], A1.x, w3v.x); ffma2(acc[1][7], A1.x, w3v.y);
                ffma2(acc[2][6], A2.x, w3v.x); ffma2(acc[2][7], A2.x, w3v.y);
                ffma2(acc[3][6], A3.x, w3v.x); ffma2(acc[3][7], A3.x, w3v.y);
            }
            {   // k-pair k2+1 (A*.y)
                const int kb = (k2 + 1) << 4;
                ulonglong2 w0  = w2i[kb + 0  + ng];
                ulonglong2 w1  = w2i[kb + 4  + ng];
                ulonglong2 w2v = w2i[kb + 8  + ng];
                ulonglong2 w3v = w2i[kb + 12 + ng];
                ffma2(acc[0][0], A0.y, w0.x);  ffma2(acc[0][1], A0.y, w0.y);
                ffma2(acc[1][0], A1.y, w0.x);  ffma2(acc[1][1], A1.y, w0.y);
                ffma2(acc[2][0], A2.y, w0.x);  ffma2(acc[2][1], A2.y, w0.y);
                ffma2(acc[3][0], A3.y, w0.x);  ffma2(acc[3][1], A3.y, w0.y);
                ffma2(acc[0][2], A0.y, w1.x);  ffma2(acc[0][3], A0.y, w1.y);
                ffma2(acc[1][2], A1.y, w1.x);  ffma2(acc[1][3], A1.y, w1.y);
                ffma2(acc[2][2], A2.y, w1.x);  ffma2(acc[2][3], A2.y, w1.y);
                ffma2(acc[3][2], A3.y, w1.x);  ffma2(acc[3][3], A3.y, w1.y);
                ffma2(acc[0][4], A0.y, w2v.x); ffma2(acc[0][5], A0.y, w2v.y);
                ffma2(acc[1][4], A1.y, w2v.x); ffma2(acc[1][5], A1.y, w2v.y);
                ffma2(acc[2][4], A2.y, w2v.x); ffma2(acc[2][5], A2.y, w2v.y);
                ffma2(acc[3][4], A3.y, w2v.x); ffma2(acc[3][5], A3.y, w2v.y);
                ffma2(acc[0][6], A0.y, w3v.x); ffma2(acc[0][7], A0.y, w3v.y);
                ffma2(acc[1][6], A1.y, w3v.x); ffma2(acc[1][7], A1.y, w3v.y);
                ffma2(acc[2][6], A2.y, w3v.x); ffma2(acc[2][7], A2.y, w3v.y);
                ffma2(acc[3][6], A3.y, w3v.x); ffma2(acc[3][7], A3.y, w3v.y);
            }
        }

        // ---- phase 3: bias+relu, dot with w3 slice, 4-lane reduce, store ----
        float b2q[8], w3q[8];
#pragma unroll
        for (int q = 0; q < 8; q++) {
            b2q[q] = b2sm[ng * 8 + q];
            w3q[q] = w3s[ng * 8 + q];
        }
        float part[4];
#pragma unroll
        for (int e = 0; e < 4; e++) {
            float p = 0.f;
#pragma unroll
            for (int n = 0; n < 8; n++) {
                float lo, hi;
                unpack2(acc[e][n], lo, hi);
                float h = fmaxf(lo + hi + b2q[n], 0.f);
                p = fmaf(h, w3q[n], p);
            }
            part[e] = p;
        }
#pragma unroll
        for (int e = 0; e < 4; e++) {
            part[e] += __shfl_xor_sync(0xffffffffu, part[e], 1);
            part[e] += __shfl_xor_sync(0xffffffffu, part[e], 2);
        }
        if (ng == 0) {
            float sig[4];
#pragma unroll
            for (int t = 0; t < 4; t++)
                sig[t] = __fdividef(1.f, 1.f + __expf(-(part[t] + b3v)));
            int ob = b + e0;
            if (ob + 3 < E) {
                *(float4*)(out + ob) = make_float4(sig[0], sig[1], sig[2], sig[3]);
            } else {
#pragma unroll
                for (int t = 0; t < 4; t++)
                    if (ob + t < E) out[ob + t] = sig[t];
            }
        }
        __syncwarp();  // protect h1u before next batch overwrites
    }
}

// ---------------------------------------------------------------------------
extern "C" void kernel_launch(void* const* d_in, const int* in_sizes, int n_in,
                              void* d_out, int out_size)
{
    const float* z  = (const float*)d_in[0];
    const void*  ei = d_in[1];
    const float* W1 = (const float*)d_in[2];
    const float* b1 = (const float*)d_in[3];
    const float* W2 = (const float*)d_in[4];
    const float* b2 = (const float*)d_in[5];
    const float* W3 = (const float*)d_in[6];
    const float* b3 = (const float*)d_in[7];
    float* out = (float*)d_out;

    int n_nodes = in_sizes[0] / INDIM;
    if (n_nodes > MAX_NODES) n_nodes = MAX_NODES;
    int E = out_size;

    int gblocks = (n_nodes + 127) / 128;
    precompute_kernel<<<gblocks, 256>>>(z, W1, b1, n_nodes);
    edge_kernel<<<296, 256>>>(ei, W2, b2, W3, b3, out, E);
}

// round 9
// speedup vs baseline: 1.7643x; 1.0161x over previous
#include <cuda_runtime.h>

#define MAX_NODES 100000
#define INDIM 128
#define HID 64

typedef unsigned long long u64;

// Scratch: per-node projections P[n][0:64]=z@W1a + b1, P[n][64:128]=z@W1b
__device__ float g_P[MAX_NODES * 128];

// ---------------------------------------------------------------------------
// f32x2 packed helpers (Blackwell — ptxas won't auto-fuse, PTX only)
__device__ __forceinline__ u64 pack2(float lo, float hi) {
    u64 r;
    asm("mov.b64 %0, {%1, %2};" : "=l"(r) : "f"(lo), "f"(hi));
    return r;
}
__device__ __forceinline__ void unpack2(u64 v, float& lo, float& hi) {
    asm("mov.b64 {%0, %1}, %2;" : "=f"(lo), "=f"(hi) : "l"(v));
}
__device__ __forceinline__ void ffma2(u64& d, u64 a, u64 b) {
    asm("fma.rn.f32x2 %0, %1, %2, %0;" : "+l"(d) : "l"(a), "l"(b));
}
__device__ __forceinline__ u64 fadd2(u64 a, u64 b) {
    u64 r;
    asm("add.rn.f32x2 %0, %1, %2;" : "=l"(r) : "l"(a), "l"(b));
    return r;
}

// ---------------------------------------------------------------------------
// Precompute GEMM: P[100K,128] = z[100K,128] @ Wcat[128,128]  (+ b1 on cols 0..63)
// Software-pipelined across K-chunks: global loads for chunk kc+1 staged into
// registers while chunk kc's FFMA2 block runs, hiding DRAM latency.
#define ZS_STRIDE 134  // u64 stride: even (16B-aligned rows), 4-way STS
__global__ __launch_bounds__(256) void precompute_kernel(
    const float* __restrict__ z, const float* __restrict__ W1,
    const float* __restrict__ b1, int n_nodes)
{
    __shared__ __align__(16) u64   zs2[32 * ZS_STRIDE];  // [k][node] dup pairs
    __shared__ __align__(16) float ws[32 * 128];         // [k][col]

    const int tid = threadIdx.x;
    const int g   = tid >> 4;
    const int c   = tid & 15;
    const int c0  = c * 8;
    const int nb  = blockIdx.x * 128;

    // staging registers: 16 z elements + 16 w elements per thread per chunk
    float zr[16], wr[16];
    // element -> (n, kq) / (kl, o) mapping is fixed per p: idx = tid + p*256
    auto load_chunk = [&](int kc) {
#pragma unroll
        for (int p = 0; p < 16; p++) {
            int idx = tid + p * 256;
            int n  = idx >> 5;
            int kq = idx & 31;
            int row = nb + n;
            zr[p] = (row < n_nodes) ? z[(size_t)row * 128 + kc * 32 + kq] : 0.f;
        }
#pragma unroll
        for (int p = 0; p < 16; p++) {
            int idx = tid + p * 256;
            int kl = idx >> 7;
            int o  = idx & 127;
            int kk = kc * 32 + kl;
            wr[p] = (o < 64) ? W1[kk * 64 + o] : W1[(128 + kk) * 64 + (o - 64)];
        }
    };

    u64 acc2[8][4];
#pragma unroll
    for (int i = 0; i < 8; i++)
#pragma unroll
        for (int j = 0; j < 4; j++) acc2[i][j] = 0ull;

    load_chunk(0);  // prologue

    for (int kc = 0; kc < 4; kc++) {
        __syncthreads();  // previous chunk's consumers done
        // store staged registers to smem
#pragma unroll
        for (int p = 0; p < 16; p++) {
            int idx = tid + p * 256;
            int n  = idx >> 5;
            int kq = idx & 31;
            zs2[kq * ZS_STRIDE + n] = pack2(zr[p], zr[p]);
        }
#pragma unroll
        for (int p = 0; p < 16; p++) {
            int idx = tid + p * 256;
            ws[idx] = wr[p];
        }
        __syncthreads();  // smem tile ready

        // issue next chunk's global loads; latency hidden by compute below
        if (kc < 3) load_chunk(kc + 1);

#pragma unroll
        for (int k = 0; k < 32; k++) {
            const u64* zrow = &zs2[k * ZS_STRIDE + g * 8];
            ulonglong2 za0 = *(const ulonglong2*)(zrow + 0);
            ulonglong2 za1 = *(const ulonglong2*)(zrow + 2);
            ulonglong2 za2 = *(const ulonglong2*)(zrow + 4);
            ulonglong2 za3 = *(const ulonglong2*)(zrow + 6);
            ulonglong2 bv0 = *(const ulonglong2*)&ws[k * 128 + c0];
            ulonglong2 bv1 = *(const ulonglong2*)&ws[k * 128 + c0 + 4];
            u64 ad[8] = {za0.x, za0.y, za1.x, za1.y, za2.x, za2.y, za3.x, za3.y};
#pragma unroll
            for (int i = 0; i < 8; i++) {
                ffma2(acc2[i][0], ad[i], bv0.x);
                ffma2(acc2[i][1], ad[i], bv0.y);
                ffma2(acc2[i][2], ad[i], bv1.x);
                ffma2(acc2[i][3], ad[i], bv1.y);
            }
        }
    }

    float bias[8];
#pragma unroll
    for (int j = 0; j < 8; j++) bias[j] = (c0 < 64) ? b1[c0 + j] : 0.f;

#pragma unroll
    for (int i = 0; i < 8; i++) {
        int row = nb + g * 8 + i;
        if (row < n_nodes) {
            float v[8];
#pragma unroll
            for (int j = 0; j < 4; j++) unpack2(acc2[i][j], v[2 * j], v[2 * j + 1]);
            float4 o0 = make_float4(v[0] + bias[0], v[1] + bias[1],
                                    v[2] + bias[2], v[3] + bias[3]);
            float4 o1 = make_float4(v[4] + bias[4], v[5] + bias[5],
                                    v[6] + bias[6], v[7] + bias[7]);
            *(float4*)&g_P[(size_t)row * 128 + c0]     = o0;
            *(float4*)&g_P[(size_t)row * 128 + c0 + 4] = o1;
        }
    }
}

// ---------------------------------------------------------------------------
// Edge kernel (unchanged from R8 — at its FFMA2 issue ceiling):
// warp processes 32-edge batches as a register-tiled GEMM.
__global__ __launch_bounds__(256, 2) void edge_kernel(
    const void* __restrict__ eidx,
    const float* __restrict__ W2, const float* __restrict__ b2,
    const float* __restrict__ W3, const float* __restrict__ b3,
    float* __restrict__ out, int E)
{
    __shared__ __align__(16) u64 h1u[8 * 32 * 32];      // [warp][edge][k-pair sw]
    __shared__ __align__(16) ulonglong2 w2i[512];       // [k2][chunk][ng] interleaved
    __shared__ float w3s[32];
    __shared__ float b2sm[32];

    const int lane = threadIdx.x & 31;
    const int wid  = threadIdx.x >> 5;
    const int eg   = lane >> 2;
    const int ng   = lane & 3;
    const int gw   = (blockIdx.x * blockDim.x + threadIdx.x) >> 5;
    const int GW   = (gridDim.x * blockDim.x) >> 5;
    const int STRIDE = GW * 32;

    for (int id = threadIdx.x; id < 512; id += 256) {
        int k2 = id >> 4;
        int cc = (id >> 2) & 3;
        int g2 = id & 3;
        int n0 = g2 * 8 + 2 * cc;
        ulonglong2 v;
        v.x = pack2(W2[(2 * k2) * 32 + n0],     W2[(2 * k2 + 1) * 32 + n0]);
        v.y = pack2(W2[(2 * k2) * 32 + n0 + 1], W2[(2 * k2 + 1) * 32 + n0 + 1]);
        w2i[id] = v;
    }
    if (threadIdx.x < 32) {
        w3s[threadIdx.x]  = W3[threadIdx.x];
        b2sm[threadIdx.x] = b2[threadIdx.x];
    }
    const float b3v = b3[0];

    const int* ei32 = (const int*)eidx;
    int oddw = ei32[2 * lane + 1] | ei32[2 * lane + 65];
    const bool is64 = (__ballot_sync(0xffffffffu, oddw != 0) == 0u);

    const char* __restrict__ Pb = (const char*)g_P;
    const unsigned lane8 = (unsigned)lane * 8u;
    const int Em1 = E - 1;

    __syncthreads();

    u64* __restrict__ h1w = &h1u[wid * 1024];

    for (int b = gw * 32; b < E; b += STRIDE) {
        int me = min(b + lane, Em1);
        int iL, jL;
        if (is64) {
            iL = (int)((const long long*)eidx)[me];
            jL = (int)((const long long*)eidx)[(long long)E + me];
        } else {
            iL = ((const int*)eidx)[me];
            jL = ((const int*)eidx)[E + me];
        }

        u64 pa[4], pb[4];
#pragma unroll
        for (int t = 0; t < 4; t++) {
            int ii = __shfl_sync(0xffffffffu, iL, t);
            int jj = __shfl_sync(0xffffffffu, jL, t);
            pa[t] = *(const u64*)(Pb + (unsigned)ii * 512u + lane8);
            pb[t] = *(const u64*)(Pb + (unsigned)jj * 512u + 256u + lane8);
        }
#pragma unroll
        for (int g = 0; g < 8; g++) {
            u64 npa[4], npb[4];
            if (g < 7) {
#pragma unroll
                for (int t = 0; t < 4; t++) {
                    int en = (g + 1) * 4 + t;
                    int ii = __shfl_sync(0xffffffffu, iL, en);
                    int jj = __shfl_sync(0xffffffffu, jL, en);
                    npa[t] = *(const u64*)(Pb + (unsigned)ii * 512u + lane8);
                    npb[t] = *(const u64*)(Pb + (unsigned)jj * 512u + 256u + lane8);
                }
            }
            const int colw = lane ^ (g << 1);
#pragma unroll
            for (int t = 0; t < 4; t++) {
                float hx, hy;
                unpack2(fadd2(pa[t], pb[t]), hx, hy);
                h1w[(g * 4 + t) * 32 + colw] = pack2(fmaxf(hx, 0.f), fmaxf(hy, 0.f));
            }
            if (g < 7) {
#pragma unroll
                for (int t = 0; t < 4; t++) { pa[t] = npa[t]; pb[t] = npb[t]; }
            }
        }
        __syncwarp();

        u64 acc[4][8];
#pragma unroll
        for (int e = 0; e < 4; e++)
#pragma unroll
            for (int n = 0; n < 8; n++) acc[e][n] = 0ull;

        const int e0  = eg * 4;
        const int egx = eg << 1;
#pragma unroll 4
        for (int k2 = 0; k2 < 32; k2 += 2) {
            const int col = k2 ^ egx;
            ulonglong2 A0 = *(const ulonglong2*)(h1w + (e0 + 0) * 32 + col);
            ulonglong2 A1 = *(const ulonglong2*)(h1w + (e0 + 1) * 32 + col);
            ulonglong2 A2 = *(const ulonglong2*)(h1w + (e0 + 2) * 32 + col);
            ulonglong2 A3 = *(const ulonglong2*)(h1w + (e0 + 3) * 32 + col);
            {
                ulonglong2 w0  = w2i[(k2 << 4) + 0  + ng];
                ulonglong2 w1  = w2i[(k2 << 4) + 4  + ng];
                ulonglong2 w2v = w2i[(k2 << 4) + 8  + ng];
                ulonglong2 w3v = w2i[(k2 << 4) + 12 + ng];
                ffma2(acc[0][0], A0.x, w0.x);  ffma2(acc[0][1], A0.x, w0.y);
                ffma2(acc[1][0], A1.x, w0.x);  ffma2(acc[1][1], A1.x, w0.y);
                ffma2(acc[2][0], A2.x, w0.x);  ffma2(acc[2][1], A2.x, w0.y);
                ffma2(acc[3][0], A3.x, w0.x);  ffma2(acc[3][1], A3.x, w0.y);
                ffma2(acc[0][2], A0.x, w1.x);  ffma2(acc[0][3], A0.x, w1.y);
                ffma2(acc[1][2], A1.x, w1.x);  ffma2(acc[1][3], A1.x, w1.y);
                ffma2(acc[2][2], A2.x, w1.x);  ffma2(acc[2][3], A2.x, w1.y);
                ffma2(acc[3][2], A3.x, w1.x);  ffma2(acc[3][3], A3.x, w1.y);
                ffma2(acc[0][4], A0.x, w2v.x); ffma2(acc[0][5], A0.x, w2v.y);
                ffma2(acc[1][4], A1.x, w2v.x); ffma2(acc[1][5], A1.x, w2v.y);
                ffma2(acc[2][4], A2.x, w2v.x); ffma2(acc[2][5], A2.x, w2v.y);
                ffma2(acc[3][4], A3.x, w2v.x); ffma2(acc[3][5], A3.x, w2v.y);
                ffma2(acc[0][6], A0.x, w3v.x); ffma2(acc[0][7], A0.x, w3v.y);
                ffma2(acc[1][6], A1.x, w3v.x); ffma2(acc[1][7], A1.x, w3v.y);
                ffma2(acc[2][6], A2.x, w3v.x); ffma2(acc[2][7], A2.x, w3v.y);
                ffma2(acc[3][6], A3.x, w3v.x); ffma2(acc[3][7], A3.x, w3v.y);
            }
            {
                const int kb = (k2 + 1) << 4;
                ulonglong2 w0  = w2i[kb + 0  + ng];
                ulonglong2 w1  = w2i[kb + 4  + ng];
                ulonglong2 w2v = w2i[kb + 8  + ng];
                ulonglong2 w3v = w2i[kb + 12 + ng];
                ffma2(acc[0][0], A0.y, w0.x);  ffma2(acc[0][1], A0.y, w0.y);
                ffma2(acc[1][0], A1.y, w0.x);  ffma2(acc[1][1], A1.y, w0.y);
                ffma2(acc[2][0], A2.y, w0.x);  ffma2(acc[2][1], A2.y, w0.y);
                ffma2(acc[3][0], A3.y, w0.x);  ffma2(acc[3][1], A3.y, w0.y);
                ffma2(acc[0][2], A0.y, w1.x);  ffma2(acc[0][3], A0.y, w1.y);
                ffma2(acc[1][2], A1.y, w1.x);  ffma2(acc[1][3], A1.y, w1.y);
                ffma2(acc[2][2], A2.y, w1.x);  ffma2(acc[2][3], A2.y, w1.y);
                ffma2(acc[3][2], A3.y, w1.x);  ffma2(acc[3][3], A3.y, w1.y);
                ffma2(acc[0][4], A0.y, w2v.x); ffma2(acc[0][5], A0.y, w2v.y);
                ffma2(acc[1][4], A1.y, w2v.x); ffma2(acc[1][5], A1.y, w2v.y);
                ffma2(acc[2][4], A2.y, w2v.x); ffma2(acc[2][5], A2.y, w2v.y);
                ffma2(acc[3][4], A3.y, w2v.x); ffma2(acc[3][5], A3.y, w2v.y);
                ffma2(acc[0][6], A0.y, w3v.x); ffma2(acc[0][7], A0.y, w3v.y);
                ffma2(acc[1][6], A1.y, w3v.x); ffma2(acc[1][7], A1.y, w3v.y);
                ffma2(acc[2][6], A2.y, w3v.x); ffma2(acc[2][7], A2.y, w3v.y);
                ffma2(acc[3][6], A3.y, w3v.x); ffma2(acc[3][7], A3.y, w3v.y);
            }
        }

        float b2q[8], w3q[8];
#pragma unroll
        for (int q = 0; q < 8; q++) {
            b2q[q] = b2sm[ng * 8 + q];
            w3q[q] = w3s[ng * 8 + q];
        }
        float part[4];
#pragma unroll
        for (int e = 0; e < 4; e++) {
            float p = 0.f;
#pragma unroll
            for (int n = 0; n < 8; n++) {
                float lo, hi;
                unpack2(acc[e][n], lo, hi);
                float h = fmaxf(lo + hi + b2q[n], 0.f);
                p = fmaf(h, w3q[n], p);
            }
            part[e] = p;
        }
#pragma unroll
        for (int e = 0; e < 4; e++) {
            part[e] += __shfl_xor_sync(0xffffffffu, part[e], 1);
            part[e] += __shfl_xor_sync(0xffffffffu, part[e], 2);
        }
        if (ng == 0) {
            float sig[4];
#pragma unroll
            for (int t = 0; t < 4; t++)
                sig[t] = __fdividef(1.f, 1.f + __expf(-(part[t] + b3v)));
            int ob = b + e0;
            if (ob + 3 < E) {
                *(float4*)(out + ob) = make_float4(sig[0], sig[1], sig[2], sig[3]);
            } else {
#pragma unroll
                for (int t = 0; t < 4; t++)
                    if (ob + t < E) out[ob + t] = sig[t];
            }
        }
        __syncwarp();
    }
}

// ---------------------------------------------------------------------------
extern "C" void kernel_launch(void* const* d_in, const int* in_sizes, int n_in,
                              void* d_out, int out_size)
{
    const float* z  = (const float*)d_in[0];
    const void*  ei = d_in[1];
    const float* W1 = (const float*)d_in[2];
    const float* b1 = (const float*)d_in[3];
    const float* W2 = (const float*)d_in[4];
    const float* b2 = (const float*)d_in[5];
    const float* W3 = (const float*)d_in[6];
    const float* b3 = (const float*)d_in[7];
    float* out = (float*)d_out;

    int n_nodes = in_sizes[0] / INDIM;
    if (n_nodes > MAX_NODES) n_nodes = MAX_NODES;
    int E = out_size;

    int gblocks = (n_nodes + 127) / 128;
    precompute_kernel<<<gblocks, 256>>>(z, W1, b1, n_nodes);
    edge_kernel<<<296, 256>>>(ei, W2, b2, W3, b3, out, E);
}

// round 11
// speedup vs baseline: 2.3981x; 1.3593x over previous
#include <cuda_runtime.h>
#include <cuda_bf16.h>
#include <cstdint>

#define MAX_NODES 100000
#define INDIM 128

typedef unsigned long long u64;

// Scratch: per-node projections P[n][0:64]=z@W1a, P[n][64:128]=z@W1b (bias-free)
__device__ float g_P[MAX_NODES * 128];
// W^T images, bf16 hi/lo, [n=128][k pitch 136] (pitch 272B -> ldmatrix conflict-free)
#define WK_PITCH 136
__device__ __align__(16) __nv_bfloat16 g_wh[128 * WK_PITCH];
__device__ __align__(16) __nv_bfloat16 g_wl[128 * WK_PITCH];

// ---------------------------------------------------------------------------
// f32x2 packed helpers (edge kernel)
__device__ __forceinline__ u64 pack2(float lo, float hi) {
    u64 r; asm("mov.b64 %0, {%1, %2};" : "=l"(r) : "f"(lo), "f"(hi)); return r;
}
__device__ __forceinline__ void unpack2(u64 v, float& lo, float& hi) {
    asm("mov.b64 {%0, %1}, %2;" : "=f"(lo), "=f"(hi) : "l"(v));
}
__device__ __forceinline__ void ffma2(u64& d, u64 a, u64 b) {
    asm("fma.rn.f32x2 %0, %1, %2, %0;" : "+l"(d) : "l"(a), "l"(b));
}
__device__ __forceinline__ u64 fadd2(u64 a, u64 b) {
    u64 r; asm("add.rn.f32x2 %0, %1, %2;" : "=l"(r) : "l"(a), "l"(b)); return r;
}

// ---------------------------------------------------------------------------
// warp-MMA helpers (baseline PTX, works on plain sm_103 target)
__device__ __forceinline__ void mma_bf16(float& d0, float& d1, float& d2, float& d3,
                                         uint32_t a0, uint32_t a1, uint32_t a2, uint32_t a3,
                                         uint32_t b0, uint32_t b1) {
    asm volatile(
        "mma.sync.aligned.m16n8k16.row.col.f32.bf16.bf16.f32 "
        "{%0,%1,%2,%3}, {%4,%5,%6,%7}, {%8,%9}, {%0,%1,%2,%3};"
        : "+f"(d0), "+f"(d1), "+f"(d2), "+f"(d3)
        : "r"(a0), "r"(a1), "r"(a2), "r"(a3), "r"(b0), "r"(b1));
}
__device__ __forceinline__ void ldmatrix_x4(uint32_t& r0, uint32_t& r1,
                                            uint32_t& r2, uint32_t& r3, uint32_t addr) {
    asm volatile("ldmatrix.sync.aligned.m8n8.x4.shared.b16 {%0,%1,%2,%3}, [%4];"
                 : "=r"(r0), "=r"(r1), "=r"(r2), "=r"(r3) : "r"(addr));
}
__device__ __forceinline__ uint32_t smem_u32(const void* p) {
    uint32_t a;
    asm("{ .reg .u64 t; cvta.to.shared.u64 t, %1; cvt.u32.u64 %0, t; }" : "=r"(a) : "l"(p));
    return a;
}
__device__ __forceinline__ uint32_t bf2(float x, float y) {
    __nv_bfloat162 t = __floats2bfloat162_rn(x, y);
    uint32_t r; asm("mov.b32 %0, %1;" : "=r"(r) : "r"(*(uint32_t*)&t)); return r;
}

// ---------------------------------------------------------------------------
// One-shot W prep: W^T bf16 hi/lo images  (Wnk[n][k] = Wcat[k][n])
__global__ void w_prep_kernel(const float* __restrict__ W1) {
    for (int idx = threadIdx.x; idx < 128 * 128; idx += blockDim.x) {
        int n = idx >> 7, k = idx & 127;
        float v = (n < 64) ? W1[k * 64 + n] : W1[(128 + k) * 64 + (n - 64)];
        __nv_bfloat16 h = __float2bfloat16_rn(v);
        __nv_bfloat16 l = __float2bfloat16_rn(v - __bfloat162float(h));
        g_wh[n * WK_PITCH + k] = h;
        g_wl[n * WK_PITCH + k] = l;
    }
}

// ---------------------------------------------------------------------------
// Precompute via warp-level bf16 MMA (3-pass hi/lo split, fp32 accumulate).
// Block = 256 thr (8 warps) computes 128 rows x 128 cols. Warp = 16 rows.
// A fragments: direct float2 global loads from z (exact m16n8k16 A layout).
// B fragments: ldmatrix.x4 from smem W^T images (2 n-tiles per load).
#define WIMG_BYTES (128 * WK_PITCH * 2)   // 34816
#define SMEM_PRE   (2 * WIMG_BYTES)       // 69632

__global__ __launch_bounds__(256) void precompute_mma_kernel(
    const float* __restrict__ z, int n_nodes)
{
    extern __shared__ __align__(16) char dsm[];
    __nv_bfloat16* swh = (__nv_bfloat16*)dsm;
    __nv_bfloat16* swl = (__nv_bfloat16*)(dsm + WIMG_BYTES);

    const int tid  = threadIdx.x;
    const int wid  = tid >> 5;
    const int lane = tid & 31;
    const int g    = lane >> 2;       // group 0..7
    const int tg   = lane & 3;        // thread-in-group
    const int nb   = blockIdx.x * 128;
    const int r0   = wid * 16;        // warp's row base within tile

    // copy W images into smem (float4)
    {
        const float4* sh = (const float4*)g_wh;
        const float4* sl = (const float4*)g_wl;
        float4* dh = (float4*)swh;
        float4* dl = (float4*)swl;
        for (int i = tid; i < WIMG_BYTES / 16; i += 256) { dh[i] = sh[i]; dl[i] = sl[i]; }
    }
    __syncthreads();

    // ldmatrix base address for this lane (x4: m0,m1 = ntile t k0/k8; m2,m3 = ntile t+1)
    const int nloc   = (lane & 7) + ((lane >> 4) << 3);
    const int koff16 = (lane >> 3) & 1;
    const uint32_t aWH = smem_u32(swh) + (uint32_t)nloc * (WK_PITCH * 2) + (uint32_t)koff16 * 16;
    const uint32_t aWL = smem_u32(swl) + (uint32_t)nloc * (WK_PITCH * 2) + (uint32_t)koff16 * 16;

    // clamped source rows for A loads
    int rowA = nb + r0 + g;
    int rowB = rowA + 8;
    const int rA = (rowA < n_nodes) ? rowA : 0;
    const int rB = (rowB < n_nodes) ? rowB : 0;
    const float* zA = z + (size_t)rA * 128 + 2 * tg;
    const float* zB = z + (size_t)rB * 128 + 2 * tg;

    float acc[16][4];
#pragma unroll
    for (int t = 0; t < 16; t++)
#pragma unroll
        for (int u = 0; u < 4; u++) acc[t][u] = 0.f;

    // prologue A raw loads (kstep 0)
    float2 raw0 = *(const float2*)(zA + 0);
    float2 raw1 = *(const float2*)(zB + 0);
    float2 raw2 = *(const float2*)(zA + 8);
    float2 raw3 = *(const float2*)(zB + 8);

#pragma unroll
    for (int ks = 0; ks < 8; ks++) {
        float2 n0v, n1v, n2v, n3v;
        if (ks < 7) {
            n0v = *(const float2*)(zA + 16 * (ks + 1));
            n1v = *(const float2*)(zB + 16 * (ks + 1));
            n2v = *(const float2*)(zA + 16 * (ks + 1) + 8);
            n3v = *(const float2*)(zB + 16 * (ks + 1) + 8);
        }
        // convert current A to hi/lo fragments
        uint32_t ah0 = bf2(raw0.x, raw0.y);
        uint32_t ah1 = bf2(raw1.x, raw1.y);
        uint32_t ah2 = bf2(raw2.x, raw2.y);
        uint32_t ah3 = bf2(raw3.x, raw3.y);
        float h;
        h = __bfloat162float(__float2bfloat16_rn(raw0.x));
        float l0x = raw0.x - h;
        h = __bfloat162float(__float2bfloat16_rn(raw0.y));
        float l0y = raw0.y - h;
        h = __bfloat162float(__float2bfloat16_rn(raw1.x));
        float l1x = raw1.x - h;
        h = __bfloat162float(__float2bfloat16_rn(raw1.y));
        float l1y = raw1.y - h;
        h = __bfloat162float(__float2bfloat16_rn(raw2.x));
        float l2x = raw2.x - h;
        h = __bfloat162float(__float2bfloat16_rn(raw2.y));
        float l2y = raw2.y - h;
        h = __bfloat162float(__float2bfloat16_rn(raw3.x));
        float l3x = raw3.x - h;
        h = __bfloat162float(__float2bfloat16_rn(raw3.y));
        float l3y = raw3.y - h;
        uint32_t al0 = bf2(l0x, l0y);
        uint32_t al1 = bf2(l1x, l1y);
        uint32_t al2 = bf2(l2x, l2y);
        uint32_t al3 = bf2(l3x, l3y);

        const uint32_t kadd = (uint32_t)ks * 32;
#pragma unroll
        for (int tp = 0; tp < 8; tp++) {
            const uint32_t toff = (uint32_t)tp * (16 * WK_PITCH * 2) + kadd;
            uint32_t wb0, wb1, wb2, wb3, vb0, vb1, vb2, vb3;
            ldmatrix_x4(wb0, wb1, wb2, wb3, aWH + toff);
            ldmatrix_x4(vb0, vb1, vb2, vb3, aWL + toff);
            float* d0 = acc[2 * tp];
            float* d1 = acc[2 * tp + 1];
            // zh*Wh
            mma_bf16(d0[0], d0[1], d0[2], d0[3], ah0, ah1, ah2, ah3, wb0, wb1);
            mma_bf16(d1[0], d1[1], d1[2], d1[3], ah0, ah1, ah2, ah3, wb2, wb3);
            // zl*Wh
            mma_bf16(d0[0], d0[1], d0[2], d0[3], al0, al1, al2, al3, wb0, wb1);
            mma_bf16(d1[0], d1[1], d1[2], d1[3], al0, al1, al2, al3, wb2, wb3);
            // zh*Wl
            mma_bf16(d0[0], d0[1], d0[2], d0[3], ah0, ah1, ah2, ah3, vb0, vb1);
            mma_bf16(d1[0], d1[1], d1[2], d1[3], ah0, ah1, ah2, ah3, vb2, vb3);
        }
        raw0 = n0v; raw1 = n1v; raw2 = n2v; raw3 = n3v;
    }

    // epilogue: D fragment (g, 2tg) / (g+8, 2tg) per ntile
    if (rowA < n_nodes) {
        float* dst = g_P + (size_t)rowA * 128 + 2 * tg;
#pragma unroll
        for (int t = 0; t < 16; t++)
            *(float2*)(dst + 8 * t) = make_float2(acc[t][0], acc[t][1]);
    }
    if (rowB < n_nodes) {
        float* dst = g_P + (size_t)rowB * 128 + 2 * tg;
#pragma unroll
        for (int t = 0; t < 16; t++)
            *(float2*)(dst + 8 * t) = make_float2(acc[t][2], acc[t][3]);
    }
}

// ---------------------------------------------------------------------------
// Edge kernel (unchanged structure; b1 added in layer 1, P is bias-free)
__global__ __launch_bounds__(256, 2) void edge_kernel(
    const void* __restrict__ eidx,
    const float* __restrict__ W2, const float* __restrict__ b2,
    const float* __restrict__ W3, const float* __restrict__ b3,
    const float* __restrict__ b1,
    float* __restrict__ out, int E)
{
    __shared__ __align__(16) u64 h1u[8 * 32 * 32];
    __shared__ __align__(16) ulonglong2 w2i[512];
    __shared__ float w3s[32];
    __shared__ float b2sm[32];

    const int lane = threadIdx.x & 31;
    const int wid  = threadIdx.x >> 5;
    const int eg   = lane >> 2;
    const int ng   = lane & 3;
    const int gw   = (blockIdx.x * blockDim.x + threadIdx.x) >> 5;
    const int GW   = (gridDim.x * blockDim.x) >> 5;
    const int STRIDE = GW * 32;

    for (int id = threadIdx.x; id < 512; id += 256) {
        int k2 = id >> 4;
        int cc = (id >> 2) & 3;
        int g2 = id & 3;
        int n0 = g2 * 8 + 2 * cc;
        ulonglong2 v;
        v.x = pack2(W2[(2 * k2) * 32 + n0],     W2[(2 * k2 + 1) * 32 + n0]);
        v.y = pack2(W2[(2 * k2) * 32 + n0 + 1], W2[(2 * k2 + 1) * 32 + n0 + 1]);
        w2i[id] = v;
    }
    if (threadIdx.x < 32) {
        w3s[threadIdx.x]  = W3[threadIdx.x];
        b2sm[threadIdx.x] = b2[threadIdx.x];
    }
    const float b3v = b3[0];
    const u64 b1p = pack2(b1[2 * lane], b1[2 * lane + 1]);

    const int* ei32 = (const int*)eidx;
    int oddw = ei32[2 * lane + 1] | ei32[2 * lane + 65];
    const bool is64 = (__ballot_sync(0xffffffffu, oddw != 0) == 0u);

    const char* __restrict__ Pb = (const char*)g_P;
    const unsigned lane8 = (unsigned)lane * 8u;
    const int Em1 = E - 1;

    __syncthreads();

    u64* __restrict__ h1w = &h1u[wid * 1024];

    for (int b = gw * 32; b < E; b += STRIDE) {
        int me = min(b + lane, Em1);
        int iL, jL;
        if (is64) {
            iL = (int)((const long long*)eidx)[me];
            jL = (int)((const long long*)eidx)[(long long)E + me];
        } else {
            iL = ((const int*)eidx)[me];
            jL = ((const int*)eidx)[E + me];
        }

        u64 pa[4], pb[4];
#pragma unroll
        for (int t = 0; t < 4; t++) {
            int ii = __shfl_sync(0xffffffffu, iL, t);
            int jj = __shfl_sync(0xffffffffu, jL, t);
            pa[t] = *(const u64*)(Pb + (unsigned)ii * 512u + lane8);
            pb[t] = *(const u64*)(Pb + (unsigned)jj * 512u + 256u + lane8);
        }
#pragma unroll
        for (int g = 0; g < 8; g++) {
            u64 npa[4], npb[4];
            if (g < 7) {
#pragma unroll
                for (int t = 0; t < 4; t++) {
                    int en = (g + 1) * 4 + t;
                    int ii = __shfl_sync(0xffffffffu, iL, en);
                    int jj = __shfl_sync(0xffffffffu, jL, en);
                    npa[t] = *(const u64*)(Pb + (unsigned)ii * 512u + lane8);
                    npb[t] = *(const u64*)(Pb + (unsigned)jj * 512u + 256u + lane8);
                }
            }
            const int colw = lane ^ (g << 1);
#pragma unroll
            for (int t = 0; t < 4; t++) {
                float hx, hy;
                unpack2(fadd2(fadd2(pa[t], pb[t]), b1p), hx, hy);
                h1w[(g * 4 + t) * 32 + colw] = pack2(fmaxf(hx, 0.f), fmaxf(hy, 0.f));
            }
            if (g < 7) {
#pragma unroll
                for (int t = 0; t < 4; t++) { pa[t] = npa[t]; pb[t] = npb[t]; }
            }
        }
        __syncwarp();

        u64 acc[4][8];
#pragma unroll
        for (int e = 0; e < 4; e++)
#pragma unroll
            for (int n = 0; n < 8; n++) acc[e][n] = 0ull;

        const int e0  = eg * 4;
        const int egx = eg << 1;
#pragma unroll 4
        for (int k2 = 0; k2 < 32; k2 += 2) {
            const int col = k2 ^ egx;
            ulonglong2 A0 = *(const ulonglong2*)(h1w + (e0 + 0) * 32 + col);
            ulonglong2 A1 = *(const ulonglong2*)(h1w + (e0 + 1) * 32 + col);
            ulonglong2 A2 = *(const ulonglong2*)(h1w + (e0 + 2) * 32 + col);
            ulonglong2 A3 = *(const ulonglong2*)(h1w + (e0 + 3) * 32 + col);
            {
                ulonglong2 w0  = w2i[(k2 << 4) + 0  + ng];
                ulonglong2 w1  = w2i[(k2 << 4) + 4  + ng];
                ulonglong2 w2v = w2i[(k2 << 4) + 8  + ng];
                ulonglong2 w3v = w2i[(k2 << 4) + 12 + ng];
                ffma2(acc[0][0], A0.x, w0.x);  ffma2(acc[0][1], A0.x, w0.y);
                ffma2(acc[1][0], A1.x, w0.x);  ffma2(acc[1][1], A1.x, w0.y);
                ffma2(acc[2][0], A2.x, w0.x);  ffma2(acc[2][1], A2.x, w0.y);
                ffma2(acc[3][0], A3.x, w0.x);  ffma2(acc[3][1], A3.x, w0.y);
                ffma2(acc[0][2], A0.x, w1.x);  ffma2(acc[0][3], A0.x, w1.y);
                ffma2(acc[1][2], A1.x, w1.x);  ffma2(acc[1][3], A1.x, w1.y);
                ffma2(acc[2][2], A2.x, w1.x);  ffma2(acc[2][3], A2.x, w1.y);
                ffma2(acc[3][2], A3.x, w1.x);  ffma2(acc[3][3], A3.x, w1.y);
                ffma2(acc[0][4], A0.x, w2v.x); ffma2(acc[0][5], A0.x, w2v.y);
                ffma2(acc[1][4], A1.x, w2v.x); ffma2(acc[1][5], A1.x, w2v.y);
                ffma2(acc[2][4], A2.x, w2v.x); ffma2(acc[2][5], A2.x, w2v.y);
                ffma2(acc[3][4], A3.x, w2v.x); ffma2(acc[3][5], A3.x, w2v.y);
                ffma2(acc[0][6], A0.x, w3v.x); ffma2(acc[0][7], A0.x, w3v.y);
                ffma2(acc[1][6], A1.x, w3v.x); ffma2(acc[1][7], A1.x, w3v.y);
                ffma2(acc[2][6], A2.x, w3v.x); ffma2(acc[2][7], A2.x, w3v.y);
                ffma2(acc[3][6], A3.x, w3v.x); ffma2(acc[3][7], A3.x, w3v.y);
            }
            {
                const int kb = (k2 + 1) << 4;
                ulonglong2 w0  = w2i[kb + 0  + ng];
                ulonglong2 w1  = w2i[kb + 4  + ng];
                ulonglong2 w2v = w2i[kb + 8  + ng];
                ulonglong2 w3v = w2i[kb + 12 + ng];
                ffma2(acc[0][0], A0.y, w0.x);  ffma2(acc[0][1], A0.y, w0.y);
                ffma2(acc[1][0], A1.y, w0.x);  ffma2(acc[1][1], A1.y, w0.y);
                ffma2(acc[2][0], A2.y, w0.x);  ffma2(acc[2][1], A2.y, w0.y);
                ffma2(acc[3][0], A3.y, w0.x);  ffma2(acc[3][1], A3.y, w0.y);
                ffma2(acc[0][2], A0.y, w1.x);  ffma2(acc[0][3], A0.y, w1.y);
                ffma2(acc[1][2], A1.y, w1.x);  ffma2(acc[1][3], A1.y, w1.y);
                ffma2(acc[2][2], A2.y, w1.x);  ffma2(acc[2][3], A2.y, w1.y);
                ffma2(acc[3][2], A3.y, w1.x);  ffma2(acc[3][3], A3.y, w1.y);
                ffma2(acc[0][4], A0.y, w2v.x); ffma2(acc[0][5], A0.y, w2v.y);
                ffma2(acc[1][4], A1.y, w2v.x); ffma2(acc[1][5], A1.y, w2v.y);
                ffma2(acc[2][4], A2.y, w2v.x); ffma2(acc[2][5], A2.y, w2v.y);
                ffma2(acc[3][4], A3.y, w2v.x); ffma2(acc[3][5], A3.y, w2v.y);
                ffma2(acc[0][6], A0.y, w3v.x); ffma2(acc[0][7], A0.y, w3v.y);
                ffma2(acc[1][6], A1.y, w3v.x); ffma2(acc[1][7], A1.y, w3v.y);
                ffma2(acc[2][6], A2.y, w3v.x); ffma2(acc[2][7], A2.y, w3v.y);
                ffma2(acc[3][6], A3.y, w3v.x); ffma2(acc[3][7], A3.y, w3v.y);
            }
        }

        float b2q[8], w3q[8];
#pragma unroll
        for (int q = 0; q < 8; q++) {
            b2q[q] = b2sm[ng * 8 + q];
            w3q[q] = w3s[ng * 8 + q];
        }
        float part[4];
#pragma unroll
        for (int e = 0; e < 4; e++) {
            float p = 0.f;
#pragma unroll
            for (int n = 0; n < 8; n++) {
                float lo, hi;
                unpack2(acc[e][n], lo, hi);
                float h = fmaxf(lo + hi + b2q[n], 0.f);
                p = fmaf(h, w3q[n], p);
            }
            part[e] = p;
        }
#pragma unroll
        for (int e = 0; e < 4; e++) {
            part[e] += __shfl_xor_sync(0xffffffffu, part[e], 1);
            part[e] += __shfl_xor_sync(0xffffffffu, part[e], 2);
        }
        if (ng == 0) {
            float sig[4];
#pragma unroll
            for (int t = 0; t < 4; t++)
                sig[t] = __fdividef(1.f, 1.f + __expf(-(part[t] + b3v)));
            int ob = b + e0;
            if (ob + 3 < E) {
                *(float4*)(out + ob) = make_float4(sig[0], sig[1], sig[2], sig[3]);
            } else {
#pragma unroll
                for (int t = 0; t < 4; t++)
                    if (ob + t < E) out[ob + t] = sig[t];
            }
        }
        __syncwarp();
    }
}

// ---------------------------------------------------------------------------
extern "C" void kernel_launch(void* const* d_in, const int* in_sizes, int n_in,
                              void* d_out, int out_size)
{
    const float* z  = (const float*)d_in[0];
    const void*  ei = d_in[1];
    const float* W1 = (const float*)d_in[2];
    const float* b1 = (const float*)d_in[3];
    const float* W2 = (const float*)d_in[4];
    const float* b2 = (const float*)d_in[5];
    const float* W3 = (const float*)d_in[6];
    const float* b3 = (const float*)d_in[7];
    float* out = (float*)d_out;

    int n_nodes = in_sizes[0] / INDIM;
    if (n_nodes > MAX_NODES) n_nodes = MAX_NODES;
    int E = out_size;

    cudaFuncSetAttribute(precompute_mma_kernel,
                         cudaFuncAttributeMaxDynamicSharedMemorySize, SMEM_PRE);

    w_prep_kernel<<<1, 256>>>(W1);
    int gblocks = (n_nodes + 127) / 128;
    precompute_mma_kernel<<<gblocks, 256, SMEM_PRE>>>(z, n_nodes);
    edge_kernel<<<296, 256>>>(ei, W2, b2, W3, b3, b1, out, E);
}

// round 12
// speedup vs baseline: 3.8225x; 1.5940x over previous
#include <cuda_runtime.h>
#include <cuda_bf16.h>
#include <cstdint>

#define MAX_NODES 100000
#define INDIM 128

typedef unsigned long long u64;

// Scratch: per-node projections P[n][0:64]=z@W1a, P[n][64:128]=z@W1b (bias-free)
__device__ float g_P[MAX_NODES * 128];
// W^T images, bf16 hi/lo, [n=128][k pitch 136]
#define WK_PITCH 136
__device__ __align__(16) __nv_bfloat16 g_wh[128 * WK_PITCH];
__device__ __align__(16) __nv_bfloat16 g_wl[128 * WK_PITCH];

// ---------------------------------------------------------------------------
// f32x2 packed helpers
__device__ __forceinline__ u64 pack2(float lo, float hi) {
    u64 r; asm("mov.b64 %0, {%1, %2};" : "=l"(r) : "f"(lo), "f"(hi)); return r;
}
__device__ __forceinline__ void unpack2(u64 v, float& lo, float& hi) {
    asm("mov.b64 {%0, %1}, %2;" : "=f"(lo), "=f"(hi) : "l"(v));
}
__device__ __forceinline__ u64 fadd2(u64 a, u64 b) {
    u64 r; asm("add.rn.f32x2 %0, %1, %2;" : "=l"(r) : "l"(a), "l"(b)); return r;
}

// ---------------------------------------------------------------------------
// warp-MMA helpers (baseline PTX, plain sm_103 target)
__device__ __forceinline__ void mma_bf16(float* d,
                                         uint32_t a0, uint32_t a1, uint32_t a2, uint32_t a3,
                                         uint32_t b0, uint32_t b1) {
    asm volatile(
        "mma.sync.aligned.m16n8k16.row.col.f32.bf16.bf16.f32 "
        "{%0,%1,%2,%3}, {%4,%5,%6,%7}, {%8,%9}, {%0,%1,%2,%3};"
        : "+f"(d[0]), "+f"(d[1]), "+f"(d[2]), "+f"(d[3])
        : "r"(a0), "r"(a1), "r"(a2), "r"(a3), "r"(b0), "r"(b1));
}
__device__ __forceinline__ void ldmatrix_x4(uint32_t& r0, uint32_t& r1,
                                            uint32_t& r2, uint32_t& r3, uint32_t addr) {
    asm volatile("ldmatrix.sync.aligned.m8n8.x4.shared.b16 {%0,%1,%2,%3}, [%4];"
                 : "=r"(r0), "=r"(r1), "=r"(r2), "=r"(r3) : "r"(addr));
}
__device__ __forceinline__ uint32_t smem_u32(const void* p) {
    uint32_t a;
    asm("{ .reg .u64 t; cvta.to.shared.u64 t, %1; cvt.u32.u64 %0, t; }" : "=r"(a) : "l"(p));
    return a;
}
__device__ __forceinline__ uint32_t bf2(float x, float y) {  // lo=x, hi=y
    __nv_bfloat162 t = __floats2bfloat162_rn(x, y);
    uint32_t r; asm("mov.b32 %0, %1;" : "=r"(r) : "r"(*(uint32_t*)&t)); return r;
}
// split a packed-pair into hi(bf16x2) + lo(bf16x2 residual)
__device__ __forceinline__ void bf16_split(float x, float y, uint32_t& hi, uint32_t& lo) {
    hi = bf2(x, y);
    float hx = __uint_as_float(hi << 16);
    float hy = __uint_as_float(hi & 0xffff0000u);
    lo = bf2(x - hx, y - hy);
}

// ---------------------------------------------------------------------------
// One-shot W1 prep (parallel): W^T bf16 hi/lo images (Wnk[n][k] = Wcat[k][n])
__global__ void w_prep_kernel(const float* __restrict__ W1) {
    int idx = blockIdx.x * 256 + threadIdx.x;
    if (idx < 128 * 128) {
        int n = idx >> 7, k = idx & 127;
        float v = (n < 64) ? W1[k * 64 + n] : W1[(128 + k) * 64 + (n - 64)];
        __nv_bfloat16 h = __float2bfloat16_rn(v);
        __nv_bfloat16 l = __float2bfloat16_rn(v - __bfloat162float(h));
        g_wh[n * WK_PITCH + k] = h;
        g_wl[n * WK_PITCH + k] = l;
    }
}

// ---------------------------------------------------------------------------
// Precompute via warp-level bf16 MMA (unchanged from R11)
#define WIMG_BYTES (128 * WK_PITCH * 2)
#define SMEM_PRE   (2 * WIMG_BYTES)

__global__ __launch_bounds__(256) void precompute_mma_kernel(
    const float* __restrict__ z, int n_nodes)
{
    extern __shared__ __align__(16) char dsm[];
    __nv_bfloat16* swh = (__nv_bfloat16*)dsm;
    __nv_bfloat16* swl = (__nv_bfloat16*)(dsm + WIMG_BYTES);

    const int tid  = threadIdx.x;
    const int wid  = tid >> 5;
    const int lane = tid & 31;
    const int g    = lane >> 2;
    const int tg   = lane & 3;
    const int nb   = blockIdx.x * 128;
    const int r0   = wid * 16;

    {
        const float4* sh = (const float4*)g_wh;
        const float4* sl = (const float4*)g_wl;
        float4* dh = (float4*)swh;
        float4* dl = (float4*)swl;
        for (int i = tid; i < WIMG_BYTES / 16; i += 256) { dh[i] = sh[i]; dl[i] = sl[i]; }
    }
    __syncthreads();

    const int nloc   = (lane & 7) + ((lane >> 4) << 3);
    const int koff16 = (lane >> 3) & 1;
    const uint32_t aWH = smem_u32(swh) + (uint32_t)nloc * (WK_PITCH * 2) + (uint32_t)koff16 * 16;
    const uint32_t aWL = smem_u32(swl) + (uint32_t)nloc * (WK_PITCH * 2) + (uint32_t)koff16 * 16;

    int rowA = nb + r0 + g;
    int rowB = rowA + 8;
    const int rA = (rowA < n_nodes) ? rowA : 0;
    const int rB = (rowB < n_nodes) ? rowB : 0;
    const float* zA = z + (size_t)rA * 128 + 2 * tg;
    const float* zB = z + (size_t)rB * 128 + 2 * tg;

    float acc[16][4];
#pragma unroll
    for (int t = 0; t < 16; t++)
#pragma unroll
        for (int u = 0; u < 4; u++) acc[t][u] = 0.f;

    float2 raw0 = *(const float2*)(zA + 0);
    float2 raw1 = *(const float2*)(zB + 0);
    float2 raw2 = *(const float2*)(zA + 8);
    float2 raw3 = *(const float2*)(zB + 8);

#pragma unroll
    for (int ks = 0; ks < 8; ks++) {
        float2 n0v, n1v, n2v, n3v;
        if (ks < 7) {
            n0v = *(const float2*)(zA + 16 * (ks + 1));
            n1v = *(const float2*)(zB + 16 * (ks + 1));
            n2v = *(const float2*)(zA + 16 * (ks + 1) + 8);
            n3v = *(const float2*)(zB + 16 * (ks + 1) + 8);
        }
        uint32_t ah0, al0, ah1, al1, ah2, al2, ah3, al3;
        bf16_split(raw0.x, raw0.y, ah0, al0);
        bf16_split(raw1.x, raw1.y, ah1, al1);
        bf16_split(raw2.x, raw2.y, ah2, al2);
        bf16_split(raw3.x, raw3.y, ah3, al3);

        const uint32_t kadd = (uint32_t)ks * 32;
#pragma unroll
        for (int tp = 0; tp < 8; tp++) {
            const uint32_t toff = (uint32_t)tp * (16 * WK_PITCH * 2) + kadd;
            uint32_t wb0, wb1, wb2, wb3, vb0, vb1, vb2, vb3;
            ldmatrix_x4(wb0, wb1, wb2, wb3, aWH + toff);
            ldmatrix_x4(vb0, vb1, vb2, vb3, aWL + toff);
            float* d0 = acc[2 * tp];
            float* d1 = acc[2 * tp + 1];
            mma_bf16(d0, ah0, ah1, ah2, ah3, wb0, wb1);
            mma_bf16(d1, ah0, ah1, ah2, ah3, wb2, wb3);
            mma_bf16(d0, al0, al1, al2, al3, wb0, wb1);
            mma_bf16(d1, al0, al1, al2, al3, wb2, wb3);
            mma_bf16(d0, ah0, ah1, ah2, ah3, vb0, vb1);
            mma_bf16(d1, ah0, ah1, ah2, ah3, vb2, vb3);
        }
        raw0 = n0v; raw1 = n1v; raw2 = n2v; raw3 = n3v;
    }

    if (rowA < n_nodes) {
        float* dst = g_P + (size_t)rowA * 128 + 2 * tg;
#pragma unroll
        for (int t = 0; t < 16; t++)
            *(float2*)(dst + 8 * t) = make_float2(acc[t][0], acc[t][1]);
    }
    if (rowB < n_nodes) {
        float* dst = g_P + (size_t)rowB * 128 + 2 * tg;
#pragma unroll
        for (int t = 0; t < 16; t++)
            *(float2*)(dst + 8 * t) = make_float2(acc[t][2], acc[t][3]);
    }
}

// ---------------------------------------------------------------------------
// Edge kernel: layer 2 on tensor cores.
// Per warp batch of 32 edges: phase1 gathers P rows, layer1 add+relu,
// bf16 hi/lo split -> smem H (pitch 144B, ldmatrix conflict-free).
// Phase2: 32x32x64 GEMM as 3-pass mma.m16n8k16 (Hh*Wh + Hl*Wh + Hh*Wl),
// W2 fragments pre-packed per-lane in smem tables.
// Phase3: D-fragment epilogue, 4-lane shfl reduce, sigmoid, store.
#define HPITCHB 144      // bytes per H row (72 bf16)
__global__ __launch_bounds__(256, 2) void edge_kernel(
    const void* __restrict__ eidx,
    const float* __restrict__ W2, const float* __restrict__ b2,
    const float* __restrict__ W3, const float* __restrict__ b3,
    const float* __restrict__ b1,
    float* __restrict__ out, int E)
{
    __shared__ __align__(16) __nv_bfloat16 Hh[8][32 * 72];
    __shared__ __align__(16) __nv_bfloat16 Hl[8][32 * 72];
    __shared__ __align__(16) uint32_t whf[1024];   // [(kt*4+nt)*2+r][lane]
    __shared__ __align__(16) uint32_t wlf[1024];
    __shared__ float w3s[32], b2sm[32];

    const int tid  = threadIdx.x;
    const int lane = tid & 31;
    const int wid  = tid >> 5;
    const int g    = lane >> 2;
    const int tg   = lane & 3;
    const int gw   = (blockIdx.x * blockDim.x + tid) >> 5;
    const int GW   = (gridDim.x * blockDim.x) >> 5;
    const int STRIDE = GW * 32;

    // --- W2 fragment tables (per-lane pre-packed) ---
    for (int id = tid; id < 1024; id += 256) {
        int l2 = id & 31;
        int r  = (id >> 5) & 1;
        int nt = (id >> 6) & 3;
        int kt = id >> 8;
        int k0 = kt * 16 + 2 * (l2 & 3) + r * 8;
        int n  = nt * 8 + (l2 >> 2);
        float v0 = W2[k0 * 32 + n];
        float v1 = W2[(k0 + 1) * 32 + n];
        uint32_t hi, lo;
        bf16_split(v0, v1, hi, lo);
        whf[id] = hi;
        wlf[id] = lo;
    }
    if (tid < 32) {
        w3s[tid]  = W3[tid];
        b2sm[tid] = b2[tid];
    }
    const float b3v = b3[0];
    const u64 b1p = pack2(b1[2 * lane], b1[2 * lane + 1]);

    // int64 vs int32 detection
    const int* ei32 = (const int*)eidx;
    int oddw = ei32[2 * lane + 1] | ei32[2 * lane + 65];
    const bool is64 = (__ballot_sync(0xffffffffu, oddw != 0) == 0u);

    const char* __restrict__ Pb = (const char*)g_P;
    const unsigned lane8 = (unsigned)lane * 8u;
    const int Em1 = E - 1;

    __syncthreads();

    char* __restrict__ Hhw = (char*)&Hh[wid][0];
    char* __restrict__ Hlw = (char*)&Hl[wid][0];
    const uint32_t lbase = (uint32_t)(lane & 15) * HPITCHB + (uint32_t)(lane >> 4) * 16;
    const uint32_t aHh = smem_u32(Hhw) + lbase;
    const uint32_t aHl = smem_u32(Hlw) + lbase;

    // b2/w3 for this lane's 8 columns (nt*8 + 2tg + r)
    float b2q[4][2], w3q[4][2];
#pragma unroll
    for (int nt = 0; nt < 4; nt++)
#pragma unroll
        for (int r = 0; r < 2; r++) {
            int col = nt * 8 + 2 * tg + r;
            b2q[nt][r] = b2sm[col];
            w3q[nt][r] = w3s[col];
        }

    for (int b = gw * 32; b < E; b += STRIDE) {
        // ---- batch index load (coalesced, clamped) ----
        int me = min(b + lane, Em1);
        int iL, jL;
        if (is64) {
            iL = (int)((const long long*)eidx)[me];
            jL = (int)((const long long*)eidx)[(long long)E + me];
        } else {
            iL = ((const int*)eidx)[me];
            jL = ((const int*)eidx)[E + me];
        }

        // ---- phase 1: gather + layer1 + bf16 split, 1-group prefetch ----
        u64 pa[4], pb[4];
#pragma unroll
        for (int t = 0; t < 4; t++) {
            int ii = __shfl_sync(0xffffffffu, iL, t);
            int jj = __shfl_sync(0xffffffffu, jL, t);
            pa[t] = *(const u64*)(Pb + (unsigned)ii * 512u + lane8);
            pb[t] = *(const u64*)(Pb + (unsigned)jj * 512u + 256u + lane8);
        }
#pragma unroll
        for (int gq = 0; gq < 8; gq++) {
            u64 npa[4], npb[4];
            if (gq < 7) {
#pragma unroll
                for (int t = 0; t < 4; t++) {
                    int en = (gq + 1) * 4 + t;
                    int ii = __shfl_sync(0xffffffffu, iL, en);
                    int jj = __shfl_sync(0xffffffffu, jL, en);
                    npa[t] = *(const u64*)(Pb + (unsigned)ii * 512u + lane8);
                    npb[t] = *(const u64*)(Pb + (unsigned)jj * 512u + 256u + lane8);
                }
            }
#pragma unroll
            for (int t = 0; t < 4; t++) {
                float hx, hy;
                unpack2(fadd2(fadd2(pa[t], pb[t]), b1p), hx, hy);
                hx = fmaxf(hx, 0.f);
                hy = fmaxf(hy, 0.f);
                uint32_t hi, lo;
                bf16_split(hx, hy, hi, lo);
                int e = gq * 4 + t;
                *(uint32_t*)(Hhw + e * HPITCHB + lane * 4) = hi;
                *(uint32_t*)(Hlw + e * HPITCHB + lane * 4) = lo;
            }
            if (gq < 7) {
#pragma unroll
                for (int t = 0; t < 4; t++) { pa[t] = npa[t]; pb[t] = npb[t]; }
            }
        }
        __syncwarp();

        // ---- phase 2: 32x32x64 GEMM on tensor cores (3-pass) ----
        float D[2][4][4];
#pragma unroll
        for (int mt = 0; mt < 2; mt++)
#pragma unroll
            for (int nt = 0; nt < 4; nt++)
#pragma unroll
                for (int u = 0; u < 4; u++) D[mt][nt][u] = 0.f;

#pragma unroll
        for (int kt = 0; kt < 4; kt++) {
            uint32_t ah[2][4], al[2][4];
            ldmatrix_x4(ah[0][0], ah[0][1], ah[0][2], ah[0][3], aHh + kt * 32);
            ldmatrix_x4(ah[1][0], ah[1][1], ah[1][2], ah[1][3], aHh + 16 * HPITCHB + kt * 32);
            ldmatrix_x4(al[0][0], al[0][1], al[0][2], al[0][3], aHl + kt * 32);
            ldmatrix_x4(al[1][0], al[1][1], al[1][2], al[1][3], aHl + 16 * HPITCHB + kt * 32);
            uint32_t bh[4][2], bl[4][2];
#pragma unroll
            for (int nt = 0; nt < 4; nt++) {
                bh[nt][0] = whf[((kt * 4 + nt) * 2 + 0) * 32 + lane];
                bh[nt][1] = whf[((kt * 4 + nt) * 2 + 1) * 32 + lane];
                bl[nt][0] = wlf[((kt * 4 + nt) * 2 + 0) * 32 + lane];
                bl[nt][1] = wlf[((kt * 4 + nt) * 2 + 1) * 32 + lane];
            }
#pragma unroll
            for (int mt = 0; mt < 2; mt++)
#pragma unroll
                for (int nt = 0; nt < 4; nt++) {
                    mma_bf16(D[mt][nt], ah[mt][0], ah[mt][1], ah[mt][2], ah[mt][3],
                             bh[nt][0], bh[nt][1]);
                    mma_bf16(D[mt][nt], al[mt][0], al[mt][1], al[mt][2], al[mt][3],
                             bh[nt][0], bh[nt][1]);
                    mma_bf16(D[mt][nt], ah[mt][0], ah[mt][1], ah[mt][2], ah[mt][3],
                             bl[nt][0], bl[nt][1]);
                }
        }

        // ---- phase 3: bias+relu, dot w3, 4-lane reduce, sigmoid, store ----
        float part[4] = {0.f, 0.f, 0.f, 0.f};
#pragma unroll
        for (int mt = 0; mt < 2; mt++)
#pragma unroll
            for (int nt = 0; nt < 4; nt++) {
                const float* c = D[mt][nt];
                part[mt * 2 + 0] = fmaf(fmaxf(c[0] + b2q[nt][0], 0.f), w3q[nt][0],
                                   fmaf(fmaxf(c[1] + b2q[nt][1], 0.f), w3q[nt][1],
                                        part[mt * 2 + 0]));
                part[mt * 2 + 1] = fmaf(fmaxf(c[2] + b2q[nt][0], 0.f), w3q[nt][0],
                                   fmaf(fmaxf(c[3] + b2q[nt][1], 0.f), w3q[nt][1],
                                        part[mt * 2 + 1]));
            }
#pragma unroll
        for (int t = 0; t < 4; t++) {
            part[t] += __shfl_xor_sync(0xffffffffu, part[t], 1);
            part[t] += __shfl_xor_sync(0xffffffffu, part[t], 2);
        }
        if (tg == 0) {
            // part[0..3] -> rows g, g+8, g+16, g+24
#pragma unroll
            for (int t = 0; t < 4; t++) {
                int row = g + t * 8;
                if (b + row < E) {
                    float sig = __fdividef(1.f, 1.f + __expf(-(part[t] + b3v)));
                    out[b + row] = sig;
                }
            }
        }
        __syncwarp();
    }
}

// ---------------------------------------------------------------------------
extern "C" void kernel_launch(void* const* d_in, const int* in_sizes, int n_in,
                              void* d_out, int out_size)
{
    const float* z  = (const float*)d_in[0];
    const void*  ei = d_in[1];
    const float* W1 = (const float*)d_in[2];
    const float* b1 = (const float*)d_in[3];
    const float* W2 = (const float*)d_in[4];
    const float* b2 = (const float*)d_in[5];
    const float* W3 = (const float*)d_in[6];
    const float* b3 = (const float*)d_in[7];
    float* out = (float*)d_out;

    int n_nodes = in_sizes[0] / INDIM;
    if (n_nodes > MAX_NODES) n_nodes = MAX_NODES;
    int E = out_size;

    cudaFuncSetAttribute(precompute_mma_kernel,
                         cudaFuncAttributeMaxDynamicSharedMemorySize, SMEM_PRE);

    w_prep_kernel<<<64, 256>>>(W1);
    int gblocks = (n_nodes + 127) / 128;
    precompute_mma_kernel<<<gblocks, 256, SMEM_PRE>>>(z, n_nodes);
    edge_kernel<<<296, 256>>>(ei, W2, b2, W3, b3, b1, out, E);
}